// round 9
// baseline (speedup 1.0000x reference)
#include <cuda_runtime.h>
#include <cuda_fp16.h>
#include <math.h>
#include <stdint.h>

#define BB   16384
#define DD   1024
#define PP   1024
#define OUTC 25
#define NCAND 16            // float4 slots per row (2 candidates each = 32)
#define MARGIN 0.35f

// ---------------- device scratch ----------------
__device__ float g_psq[PP];
__device__ float g_v1[PP];
__device__ float g_v2[PP];
__device__ float g_PW[PP * DD];
__device__ int   g_labels[BB];
__device__ float g_lam[BB];
__device__ float4 g_top2[(size_t)BB * NCAND];
__device__ float g_part[(size_t)16 * BB * OUTC];   // class-head partials

__device__ __half g_pa_hi[(size_t)BB * DD];
__device__ __half g_pr_hi[(size_t)PP * DD];
__device__ __half g_pr_lo[(size_t)PP * DD];
__device__ __half g_fc_hi[(size_t)PP * DD];
__device__ __half g_wt_hi[(size_t)DD * DD];
__device__ __half g_wt_lo[(size_t)DD * DD];
__device__ __half g_mx_hi[(size_t)BB * DD];

// ---------------- helpers ----------------
__device__ __forceinline__ uint32_t smem_u32(const void* p) {
    uint32_t a;
    asm("{ .reg .u64 t; cvta.to.shared.u64 t, %1; cvt.u32.u64 %0, t; }" : "=r"(a) : "l"(p));
    return a;
}
__device__ __forceinline__ void ldsm4(uint32_t r[4], uint32_t addr) {
    asm volatile("ldmatrix.sync.aligned.m8n8.x4.shared.b16 {%0,%1,%2,%3}, [%4];"
                 : "=r"(r[0]), "=r"(r[1]), "=r"(r[2]), "=r"(r[3]) : "r"(addr));
}
__device__ __forceinline__ void mma16816(float c[4], const uint32_t a[4],
                                         uint32_t b0, uint32_t b1) {
    asm volatile("mma.sync.aligned.m16n8k16.row.col.f32.f16.f16.f32 "
                 "{%0,%1,%2,%3}, {%4,%5,%6,%7}, {%8,%9}, {%0,%1,%2,%3};"
                 : "+f"(c[0]), "+f"(c[1]), "+f"(c[2]), "+f"(c[3])
                 : "r"(a[0]), "r"(a[1]), "r"(a[2]), "r"(a[3]), "r"(b0), "r"(b1));
}
__device__ __forceinline__ uint32_t pk2h(float a, float b) {
    __half2 t;
    t.x = __float2half(a); t.y = __float2half(b);
    return *reinterpret_cast<uint32_t*>(&t);
}
__device__ __forceinline__ void top2_upd(float s, int idx, float& v1, int& i1,
                                         float& v2, int& i2) {
    if (s < v1 || (s == v1 && idx < i1)) { v2 = v1; i2 = i1; v1 = s; i1 = idx; }
    else if (s < v2 || (s == v2 && idx < i2)) { v2 = s; i2 = idx; }
}
__device__ __forceinline__ void top2_merge(float w1, int j1, float w2, int j2,
                                           float& v1, int& i1, float& v2, int& i2) {
    top2_upd(w1, j1, v1, i1, v2, i2);
    top2_upd(w2, j2, v1, i1, v2, i2);
}

// =================================================================
// prep: p_sq, v1, v2
// =================================================================
__global__ __launch_bounds__(256) void prep_kernel(
    const float* __restrict__ protos, const float* __restrict__ lin_w)
{
    int p = blockIdx.x, t = threadIdx.x;
    float sq = 0.f, a1 = 0.f, a2 = 0.f;
    const float* row = protos + (size_t)p * DD;
    for (int k = t; k < DD; k += 256) {
        float v = row[k];
        sq = fmaf(v, v, sq);
        a1 = fmaf(v, lin_w[k], a1);
        a2 = fmaf(v, lin_w[DD + k], a2);
    }
    __shared__ float s1[256], s2[256], s3[256];
    s1[t] = sq; s2[t] = a1; s3[t] = a2;
    __syncthreads();
    for (int off = 128; off; off >>= 1) {
        if (t < off) { s1[t] += s1[t+off]; s2[t] += s2[t+off]; s3[t] += s3[t+off]; }
        __syncthreads();
    }
    if (t == 0) { g_psq[p] = s1[0]; g_v1[p] = s2[0]; g_v2[p] = s3[0]; }
}

// =================================================================
// convert fp32 -> fp16 (hi only)
// =================================================================
__global__ __launch_bounds__(256) void convert_kernel(
    const float* __restrict__ src, __half* __restrict__ hi, int n4)
{
    int i = blockIdx.x * 256 + threadIdx.x;
    if (i >= n4) return;
    float4 v = reinterpret_cast<const float4*>(src)[i];
    reinterpret_cast<uint32_t*>(hi)[2*i]   = pk2h(v.x, v.y);
    reinterpret_cast<uint32_t*>(hi)[2*i+1] = pk2h(v.z, v.w);
}

// =================================================================
// split fp32 -> fp16 hi + lo
// =================================================================
__global__ __launch_bounds__(256) void split_kernel(
    const float* __restrict__ src, __half* __restrict__ hi,
    __half* __restrict__ lo, int n4)
{
    int i = blockIdx.x * 256 + threadIdx.x;
    if (i >= n4) return;
    float4 v = reinterpret_cast<const float4*>(src)[i];
    uint32_t h0 = pk2h(v.x, v.y), h1 = pk2h(v.z, v.w);
    __half2* hv0 = reinterpret_cast<__half2*>(&h0);
    __half2* hv1 = reinterpret_cast<__half2*>(&h1);
    uint32_t l0 = pk2h(v.x - __half2float(hv0->x), v.y - __half2float(hv0->y));
    uint32_t l1 = pk2h(v.z - __half2float(hv1->x), v.w - __half2float(hv1->y));
    reinterpret_cast<uint32_t*>(hi)[2*i]   = h0;
    reinterpret_cast<uint32_t*>(hi)[2*i+1] = h1;
    reinterpret_cast<uint32_t*>(lo)[2*i]   = l0;
    reinterpret_cast<uint32_t*>(lo)[2*i+1] = l1;
}

// =================================================================
// transpose + split: WT[n][k] = W[k][n], fp16 hi/lo
// =================================================================
__global__ __launch_bounds__(256) void splitT_kernel(
    const float* __restrict__ W, __half* __restrict__ hiT,
    __half* __restrict__ loT)
{
    __shared__ float tile[32][33];
    int n0 = blockIdx.x * 32, k0 = blockIdx.y * 32;
    int tx = threadIdx.x & 31, ty = threadIdx.x >> 5;
#pragma unroll
    for (int i = 0; i < 4; i++) {
        int kk = ty + i * 8;
        tile[kk][tx] = W[(size_t)(k0 + kk) * DD + n0 + tx];
    }
    __syncthreads();
#pragma unroll
    for (int i = 0; i < 4; i++) {
        int a = ty + i * 8;
        float v = tile[tx][a];
        __half h = __float2half(v);
        hiT[(size_t)(n0 + a) * DD + k0 + tx] = h;
        loT[(size_t)(n0 + a) * DD + k0 + tx] = __float2half(v - __half2float(h));
    }
}

// =================================================================
// Generic GEMM body (device). 128x128 tile, BK=32, NST-stage cp.async.
// PASSES 1: A single, B single ; PASSES 3: A hi/lo x B hi/lo (3 mma)
// MODE 0: per-warp top2(psq-2*dot) -> g_top2
// MODE 2: plain store, stride DD (PW)
// MODE 3: fused class-head partial (leaky(v+bias) . cw) -> g_part
// =================================================================
template <int PASSES, int MODE, int NST>
__device__ __forceinline__ void gemm_body(
    int row0, int col0, int colTile,
    const __half* __restrict__ Ahi, const __half* __restrict__ Alo,
    const __half* __restrict__ Bhi, const __half* __restrict__ Blo,
    const float* __restrict__ bias, float* __restrict__ outp,
    const float* __restrict__ cw, char* smem)
{
    constexpr int TILES = (PASSES == 3) ? 4 : 2;
    constexpr int STB = TILES * 8192;
    constexpr int BOFF = (PASSES == 1) ? 8192 : 16384;
    constexpr int DEPTH = NST - 1;
    const uint32_t sb = smem_u32(smem);
    const int tid = threadIdx.x;
    const int lane = tid & 31;
    const int w = tid >> 5;
    const int wm = w & 3;
    const int wn = w >> 2;

    const int q  = lane >> 3;
    const int lr = lane & 7;
    const int achk = q >> 1;
    const int bchk = q & 1;
    int arow[2], brow[4];
#pragma unroll
    for (int mi = 0; mi < 2; mi++) arow[mi] = wm*32 + mi*16 + ((q & 1) << 3) + lr;
#pragma unroll
    for (int ng = 0; ng < 4; ng++) brow[ng] = wn*64 + ng*16 + ((q >> 1) << 3) + lr;

    float c[2][8][4];
#pragma unroll
    for (int mi = 0; mi < 2; mi++)
#pragma unroll
        for (int nf = 0; nf < 8; nf++)
#pragma unroll
            for (int j = 0; j < 4; j++) c[mi][nf][j] = 0.f;

    auto issue = [&](int st, int kt) {
        const int k0 = kt << 5;
        const uint32_t sbase = sb + st * STB;
#pragma unroll
        for (int it = 0; it < TILES * 2; it++) {
            int ch = it * 256 + tid;
            int t = ch >> 9;
            int within = ch & 511;
            int r = within >> 2, cc = within & 3;
            const __half* src;
            int rbase;
            if (PASSES == 1) {
                src = (t == 0) ? Ahi : Bhi;
                rbase = (t == 0) ? row0 : col0;
            } else {
                src = (t == 0) ? Ahi : (t == 1) ? Alo : (t == 2) ? Bhi : Blo;
                rbase = (t < 2) ? row0 : col0;
            }
            const void* g = src + (size_t)(rbase + r) * DD + k0 + cc * 8;
            uint32_t s = sbase + t * 8192 + r * 64 + ((cc ^ ((r >> 1) & 3)) << 4);
            asm volatile("cp.async.cg.shared.global [%0], [%1], 16;" :: "r"(s), "l"(g));
        }
        asm volatile("cp.async.commit_group;" ::: "memory");
    };

    auto compute = [&](int st) {
        const uint32_t sbase = sb + st * STB;
#pragma unroll
        for (int ks = 0; ks < 2; ks++) {
            uint32_t ah[2][4], al[2][4], bh[4][4], bl[4][4];
#pragma unroll
            for (int mi = 0; mi < 2; mi++) {
                uint32_t ra = sbase + arow[mi] * 64 +
                              ((((ks << 1) | achk) ^ ((arow[mi] >> 1) & 3)) << 4);
                ldsm4(ah[mi], ra);
                if (PASSES == 3) ldsm4(al[mi], ra + 8192);
            }
#pragma unroll
            for (int ng = 0; ng < 4; ng++) {
                uint32_t rb = sbase + BOFF + brow[ng] * 64 +
                              ((((ks << 1) | bchk) ^ ((brow[ng] >> 1) & 3)) << 4);
                ldsm4(bh[ng], rb);
                if (PASSES == 3) ldsm4(bl[ng], rb + 8192);
            }
#pragma unroll
            for (int mi = 0; mi < 2; mi++)
#pragma unroll
                for (int ng = 0; ng < 4; ng++)
#pragma unroll
                    for (int h = 0; h < 2; h++) {
                        int nf = ng * 2 + h;
                        mma16816(c[mi][nf], ah[mi], bh[ng][h*2], bh[ng][h*2+1]);
                        if (PASSES == 3) {
                            mma16816(c[mi][nf], ah[mi], bl[ng][h*2], bl[ng][h*2+1]);
                            mma16816(c[mi][nf], al[mi], bh[ng][h*2], bh[ng][h*2+1]);
                        }
                    }
        }
    };

    const int NK = DD / 32;
#pragma unroll
    for (int i = 0; i < DEPTH; i++) issue(i, i);
    for (int kt = 0; kt < NK; kt++) {
        const int rem = NK - 1 - kt;
        if (DEPTH == 3) {
            if (rem >= 2)      asm volatile("cp.async.wait_group 2;" ::: "memory");
            else if (rem == 1) asm volatile("cp.async.wait_group 1;" ::: "memory");
            else               asm volatile("cp.async.wait_group 0;" ::: "memory");
        } else {
            if (rem >= 1)      asm volatile("cp.async.wait_group 1;" ::: "memory");
            else               asm volatile("cp.async.wait_group 0;" ::: "memory");
        }
        __syncthreads();
        compute(kt % NST);
        if (kt + DEPTH < NK) issue((kt + DEPTH) % NST, kt + DEPTH);
        __syncthreads();
    }
    __syncthreads();

    if (MODE == 0) {
#pragma unroll
        for (int mi = 0; mi < 2; mi++)
#pragma unroll
            for (int rh = 0; rh < 2; rh++) {
                int lrow_ = wm*32 + mi*16 + rh*8 + (lane >> 2);
                float v1 = 3.4e38f, v2 = 3.4e38f;
                int i1 = 0, i2 = 0;
#pragma unroll
                for (int nf = 0; nf < 8; nf++) {
                    int col = col0 + wn*64 + nf*8 + ((lane & 3) << 1);
                    float s0 = bias[col]     - 2.f * c[mi][nf][rh*2];
                    float s1 = bias[col + 1] - 2.f * c[mi][nf][rh*2+1];
                    top2_upd(s0, col,     v1, i1, v2, i2);
                    top2_upd(s1, col + 1, v1, i1, v2, i2);
                }
#pragma unroll
                for (int d = 1; d <= 2; d <<= 1) {
                    float w1 = __shfl_xor_sync(0xffffffffu, v1, d);
                    float w2 = __shfl_xor_sync(0xffffffffu, v2, d);
                    int   j1 = __shfl_xor_sync(0xffffffffu, i1, d);
                    int   j2 = __shfl_xor_sync(0xffffffffu, i2, d);
                    top2_merge(w1, j1, w2, j2, v1, i1, v2, i2);
                }
                if ((lane & 3) == 0)
                    reinterpret_cast<float4*>(outp)[(size_t)(row0 + lrow_) * NCAND
                                                    + colTile * 2 + wn] =
                        make_float4(v1, __int_as_float(i1), v2, __int_as_float(i2));
            }
    } else if (MODE == 2) {
#pragma unroll
        for (int mi = 0; mi < 2; mi++)
#pragma unroll
            for (int rh = 0; rh < 2; rh++) {
                int r = row0 + wm*32 + mi*16 + rh*8 + (lane >> 2);
#pragma unroll
                for (int nf = 0; nf < 8; nf++) {
                    int col = col0 + wn*64 + nf*8 + ((lane & 3) << 1);
                    float2 o = {c[mi][nf][rh*2], c[mi][nf][rh*2+1]};
                    *reinterpret_cast<float2*>(&outp[(size_t)r * DD + col]) = o;
                }
            }
    } else {   // MODE 3: fused class-head partial
        float* cwsm = reinterpret_cast<float*>(smem);      // [25][128]
        float* bsm  = cwsm + OUTC * 128;                   // [128]
        for (int i = tid; i < OUTC * 128; i += 256) {
            int o = i >> 7, cl = i & 127;
            cwsm[i] = cw[(size_t)o * PP + col0 + cl];
        }
        if (tid < 128) bsm[tid] = bias[col0 + tid];
        __syncthreads();
#pragma unroll
        for (int mi = 0; mi < 2; mi++)
#pragma unroll
            for (int rh = 0; rh < 2; rh++) {
                int rowL = wm*32 + mi*16 + rh*8 + (lane >> 2);
                float acc[OUTC];
#pragma unroll
                for (int o = 0; o < OUTC; o++) acc[o] = 0.f;
#pragma unroll
                for (int nf = 0; nf < 8; nf++)
#pragma unroll
                    for (int jj = 0; jj < 2; jj++) {
                        int cl = wn*64 + nf*8 + ((lane & 3) << 1) + jj;
                        float v = c[mi][nf][rh*2 + jj] + bsm[cl];
                        v = v > 0.f ? v : 0.01f * v;
#pragma unroll
                        for (int o = 0; o < OUTC; o++)
                            acc[o] = fmaf(v, cwsm[o * 128 + cl], acc[o]);
                    }
#pragma unroll
                for (int o = 0; o < OUTC; o++) {
                    acc[o] += __shfl_down_sync(0xffffffffu, acc[o], 1);
                    acc[o] += __shfl_down_sync(0xffffffffu, acc[o], 2);
                }
                if ((lane & 3) == 0) {
                    int t = colTile * 2 + wn;
                    float* dst = outp + ((size_t)t * BB + row0 + rowL) * OUTC;
#pragma unroll
                    for (int o = 0; o < OUTC; o++) dst[o] = acc[o];
                }
            }
    }
}

// =================================================================
// fat kernel: dist GEMM (y<128) + PW GEMM (y>=128) in one launch
// =================================================================
__global__ __launch_bounds__(256)
void fat_dist_pw_kernel()
{
    extern __shared__ char smem[];
    if (blockIdx.y < 128) {
        gemm_body<1, 0, 4>(blockIdx.y * 128, blockIdx.x * 128, blockIdx.x,
                           g_pa_hi, nullptr, g_pr_hi, nullptr,
                           g_psq, (float*)g_top2, nullptr, smem);
    } else {
        gemm_body<3, 2, 3>((blockIdx.y - 128) * 128, blockIdx.x * 128, blockIdx.x,
                           g_pr_hi, g_pr_lo, g_wt_hi, g_wt_lo,
                           nullptr, g_PW, nullptr, smem);
    }
}

// =================================================================
// logits GEMM with fused class-head partial epilogue
// =================================================================
__global__ __launch_bounds__(256)
void logits_class_kernel(const float* __restrict__ bias, const float* __restrict__ cw)
{
    extern __shared__ char smem[];
    gemm_body<1, 3, 4>(blockIdx.y * 128, blockIdx.x * 128, blockIdx.x,
                       g_mx_hi, nullptr, g_fc_hi, nullptr,
                       bias, g_part, cw, smem);
}

// =================================================================
// reduce class partials: out[b][o] = sum_t part[t][b][o] + cb[o]
// =================================================================
__global__ __launch_bounds__(256)
void reduce_class_kernel(const float* __restrict__ cb, float* __restrict__ out)
{
    int i = blockIdx.x * 256 + threadIdx.x;
    if (i >= BB * OUTC) return;
    int o = i % OUTC;
    float s = cb[o];
#pragma unroll
    for (int t = 0; t < 16; t++)
        s += g_part[(size_t)t * BB * OUTC + i];
    out[i] = s;
}

// =================================================================
// 32 candidates/row; exact fp64 rescue over all within MARGIN
// =================================================================
__global__ __launch_bounds__(256)
void argmin_reduce_kernel(const float* __restrict__ patient, const float* __restrict__ protos)
{
    int w = (blockIdx.x * 256 + threadIdx.x) >> 5;
    int lane = threadIdx.x & 31;
    if (w >= BB) return;

    float4 qd = g_top2[(size_t)w * NCAND + (lane >> 1)];
    float val;
    int idx;
    if (lane & 1) { val = qd.z; idx = __float_as_int(qd.w); }
    else          { val = qd.x; idx = __float_as_int(qd.y); }

    float vmin = val;
#pragma unroll
    for (int d = 16; d; d >>= 1)
        vmin = fminf(vmin, __shfl_xor_sync(0xffffffffu, vmin, d));

    bool flag = (val < vmin + MARGIN);
    unsigned mask = __ballot_sync(0xffffffffu, flag);

    if (__popc(mask) == 1) {
        if (flag) g_labels[w] = idx;
        return;
    }

    const float* x = patient + (size_t)w * DD;
    double bestd = 1.0e300;
    int besti = 0x7FFFFFFF;
    while (mask) {
        int src = __ffs(mask) - 1;
        mask &= mask - 1;
        int ci = __shfl_sync(0xffffffffu, idx, src);
        const float* pr = protos + (size_t)ci * DD;
        double acc = 0.0;
        for (int k = lane; k < DD; k += 32)
            acc += (double)x[k] * (double)pr[k];
#pragma unroll
        for (int d = 16; d; d >>= 1)
            acc += __shfl_down_sync(0xffffffffu, acc, d);
        if (lane == 0) {
            double d2 = (double)g_psq[ci] - 2.0 * acc;
            if (d2 < bestd || (d2 == bestd && ci < besti)) { bestd = d2; besti = ci; }
        }
    }
    if (lane == 0) g_labels[w] = besti;
}

// =================================================================
// lam[b] = sigmoid(PW[la].protos[lb] + bil_b + v1[la] + v2[lb])
// =================================================================
__global__ __launch_bounds__(256)
void lam_kernel(const int* __restrict__ index, const float* __restrict__ bilinear_b,
                const float* __restrict__ protos)
{
    int w = (blockIdx.x * 256 + threadIdx.x) >> 5;
    int lane = threadIdx.x & 31;
    if (w >= BB) return;
    int la = g_labels[w];
    int lb = g_labels[index[w]];
    const float4* a = reinterpret_cast<const float4*>(g_PW + (size_t)la * DD);
    const float4* p = reinterpret_cast<const float4*>(protos + (size_t)lb * DD);
    float acc = 0.f;
    for (int k = lane; k < DD / 4; k += 32) {
        float4 u = a[k], v = p[k];
        acc = fmaf(u.x, v.x, acc); acc = fmaf(u.y, v.y, acc);
        acc = fmaf(u.z, v.z, acc); acc = fmaf(u.w, v.w, acc);
    }
#pragma unroll
    for (int off = 16; off; off >>= 1) acc += __shfl_down_sync(0xffffffffu, acc, off);
    if (lane == 0) {
        float s = acc + bilinear_b[0] + g_v1[la] + g_v2[lb];
        g_lam[w] = 1.f / (1.f + expf(-s));
    }
}

// =================================================================
// mixed = lam*x + (1-lam)*x[index]; emit fp16 (hi only)
// =================================================================
__global__ __launch_bounds__(256)
void mix_kernel(const float* __restrict__ patient, const int* __restrict__ index)
{
    int b = blockIdx.x;
    float lam = g_lam[b], oml = 1.f - lam;
    int ib = index[b];
    int t = threadIdx.x;
    float4 a = reinterpret_cast<const float4*>(patient + (size_t)b * DD)[t];
    float4 c = reinterpret_cast<const float4*>(patient + (size_t)ib * DD)[t];
    float m0 = lam * a.x + oml * c.x, m1 = lam * a.y + oml * c.y;
    float m2 = lam * a.z + oml * c.z, m3 = lam * a.w + oml * c.w;
    size_t o = (size_t)b * (DD / 2) + 2 * t;
    reinterpret_cast<uint32_t*>(g_mx_hi)[o]     = pk2h(m0, m1);
    reinterpret_cast<uint32_t*>(g_mx_hi)[o + 1] = pk2h(m2, m3);
}

// =================================================================
// launch
// =================================================================
extern "C" void kernel_launch(void* const* d_in, const int* in_sizes, int n_in,
                              void* d_out, int out_size)
{
    const float* patient    = (const float*)d_in[0];
    const float* protos     = (const float*)d_in[1];
    const int*   index      = (const int*)  d_in[2];
    const float* bilinear_w = (const float*)d_in[3];
    const float* bilinear_b = (const float*)d_in[4];
    const float* lin_w      = (const float*)d_in[5];
    const float* proto_fc_w = (const float*)d_in[6];
    const float* proto_fc_b = (const float*)d_in[7];
    const float* class_fc_w = (const float*)d_in[8];
    const float* class_fc_b = (const float*)d_in[9];
    float* out = (float*)d_out;

    __half *pPaHi, *pPrHi, *pPrLo, *pFcHi, *pWtHi, *pWtLo;
    cudaGetSymbolAddress((void**)&pPaHi, g_pa_hi);
    cudaGetSymbolAddress((void**)&pPrHi, g_pr_hi);
    cudaGetSymbolAddress((void**)&pPrLo, g_pr_lo);
    cudaGetSymbolAddress((void**)&pFcHi, g_fc_hi);
    cudaGetSymbolAddress((void**)&pWtHi, g_wt_hi);
    cudaGetSymbolAddress((void**)&pWtLo, g_wt_lo);

    const int SM_FAT = 3 * 4 * 8192;           // 98304 (max of both paths)
    const int SM_LOG = 4 * 2 * 8192 + 4096;    // 69632
    cudaFuncSetAttribute(fat_dist_pw_kernel, cudaFuncAttributeMaxDynamicSharedMemorySize, SM_FAT);
    cudaFuncSetAttribute(logits_class_kernel, cudaFuncAttributeMaxDynamicSharedMemorySize, SM_LOG);

    prep_kernel<<<PP, 256>>>(protos, lin_w);

    convert_kernel<<<(BB * DD / 4) / 256, 256>>>(patient, pPaHi, BB * DD / 4);
    split_kernel<<<(PP * DD / 4) / 256, 256>>>(protos, pPrHi, pPrLo, PP * DD / 4);
    convert_kernel<<<(PP * DD / 4) / 256, 256>>>(proto_fc_w, pFcHi, PP * DD / 4);
    splitT_kernel<<<dim3(32, 32), 256>>>(bilinear_w, pWtHi, pWtLo);

    // dist GEMM (1-pass) + PW GEMM (3-pass) overlapped in one launch
    fat_dist_pw_kernel<<<dim3(8, 136), 256, SM_FAT>>>();

    argmin_reduce_kernel<<<BB / 8, 256>>>(patient, protos);

    lam_kernel<<<BB / 8, 256>>>(index, bilinear_b, protos);

    mix_kernel<<<BB, 256>>>(patient, index);

    // logits GEMM (1-pass) with fused class-head partial epilogue
    logits_class_kernel<<<dim3(8, 128), 256, SM_LOG>>>(proto_fc_b, class_fc_w);

    reduce_class_kernel<<<(BB * OUTC + 255) / 256, 256>>>(class_fc_b, out);
}

// round 11
// speedup vs baseline: 1.3247x; 1.3247x over previous
#include <cuda_runtime.h>
#include <cuda_fp16.h>
#include <math.h>
#include <stdint.h>

#define BB   16384
#define DD   1024
#define PP   1024
#define OUTC 25
#define NCAND 16            // float4 slots per row (2 candidates each = 32)
#define MARGIN 0.35f

// ---------------- device scratch ----------------
__device__ float g_psq[PP];
__device__ float g_v1[PP];
__device__ float g_v2[PP];
__device__ float g_PW[PP * DD];
__device__ int   g_labels[BB];
__device__ float g_lam[BB];
__device__ float4 g_top2[(size_t)BB * NCAND];
__device__ float g_part[(size_t)8 * BB * OUTC];   // class-head partials (per col-tile)

__device__ __half g_pa_hi[(size_t)BB * DD];
__device__ __half g_pr_hi[(size_t)PP * DD];
__device__ __half g_pr_lo[(size_t)PP * DD];
__device__ __half g_fc_hi[(size_t)PP * DD];
__device__ __half g_wt_hi[(size_t)DD * DD];
__device__ __half g_wt_lo[(size_t)DD * DD];
__device__ __half g_mx_hi[(size_t)BB * DD];

// ---------------- helpers ----------------
__device__ __forceinline__ uint32_t smem_u32(const void* p) {
    uint32_t a;
    asm("{ .reg .u64 t; cvta.to.shared.u64 t, %1; cvt.u32.u64 %0, t; }" : "=r"(a) : "l"(p));
    return a;
}
__device__ __forceinline__ void ldsm4(uint32_t r[4], uint32_t addr) {
    asm volatile("ldmatrix.sync.aligned.m8n8.x4.shared.b16 {%0,%1,%2,%3}, [%4];"
                 : "=r"(r[0]), "=r"(r[1]), "=r"(r[2]), "=r"(r[3]) : "r"(addr));
}
__device__ __forceinline__ void mma16816(float c[4], const uint32_t a[4],
                                         uint32_t b0, uint32_t b1) {
    asm volatile("mma.sync.aligned.m16n8k16.row.col.f32.f16.f16.f32 "
                 "{%0,%1,%2,%3}, {%4,%5,%6,%7}, {%8,%9}, {%0,%1,%2,%3};"
                 : "+f"(c[0]), "+f"(c[1]), "+f"(c[2]), "+f"(c[3])
                 : "r"(a[0]), "r"(a[1]), "r"(a[2]), "r"(a[3]), "r"(b0), "r"(b1));
}
__device__ __forceinline__ uint32_t pk2h(float a, float b) {
    __half2 t;
    t.x = __float2half(a); t.y = __float2half(b);
    return *reinterpret_cast<uint32_t*>(&t);
}
__device__ __forceinline__ void top2_upd(float s, int idx, float& v1, int& i1,
                                         float& v2, int& i2) {
    if (s < v1 || (s == v1 && idx < i1)) { v2 = v1; i2 = i1; v1 = s; i1 = idx; }
    else if (s < v2 || (s == v2 && idx < i2)) { v2 = s; i2 = idx; }
}
__device__ __forceinline__ void top2_merge(float w1, int j1, float w2, int j2,
                                           float& v1, int& i1, float& v2, int& i2) {
    top2_upd(w1, j1, v1, i1, v2, i2);
    top2_upd(w2, j2, v1, i1, v2, i2);
}

// =================================================================
// prep: p_sq, v1, v2
// =================================================================
__global__ __launch_bounds__(256) void prep_kernel(
    const float* __restrict__ protos, const float* __restrict__ lin_w)
{
    int p = blockIdx.x, t = threadIdx.x;
    float sq = 0.f, a1 = 0.f, a2 = 0.f;
    const float* row = protos + (size_t)p * DD;
    for (int k = t; k < DD; k += 256) {
        float v = row[k];
        sq = fmaf(v, v, sq);
        a1 = fmaf(v, lin_w[k], a1);
        a2 = fmaf(v, lin_w[DD + k], a2);
    }
    __shared__ float s1[256], s2[256], s3[256];
    s1[t] = sq; s2[t] = a1; s3[t] = a2;
    __syncthreads();
    for (int off = 128; off; off >>= 1) {
        if (t < off) { s1[t] += s1[t+off]; s2[t] += s2[t+off]; s3[t] += s3[t+off]; }
        __syncthreads();
    }
    if (t == 0) { g_psq[p] = s1[0]; g_v1[p] = s2[0]; g_v2[p] = s3[0]; }
}

// =================================================================
// convert fp32 -> fp16 (hi only)
// =================================================================
__global__ __launch_bounds__(256) void convert_kernel(
    const float* __restrict__ src, __half* __restrict__ hi, int n4)
{
    int i = blockIdx.x * 256 + threadIdx.x;
    if (i >= n4) return;
    float4 v = reinterpret_cast<const float4*>(src)[i];
    reinterpret_cast<uint32_t*>(hi)[2*i]   = pk2h(v.x, v.y);
    reinterpret_cast<uint32_t*>(hi)[2*i+1] = pk2h(v.z, v.w);
}

// =================================================================
// split fp32 -> fp16 hi + lo
// =================================================================
__global__ __launch_bounds__(256) void split_kernel(
    const float* __restrict__ src, __half* __restrict__ hi,
    __half* __restrict__ lo, int n4)
{
    int i = blockIdx.x * 256 + threadIdx.x;
    if (i >= n4) return;
    float4 v = reinterpret_cast<const float4*>(src)[i];
    uint32_t h0 = pk2h(v.x, v.y), h1 = pk2h(v.z, v.w);
    __half2* hv0 = reinterpret_cast<__half2*>(&h0);
    __half2* hv1 = reinterpret_cast<__half2*>(&h1);
    uint32_t l0 = pk2h(v.x - __half2float(hv0->x), v.y - __half2float(hv0->y));
    uint32_t l1 = pk2h(v.z - __half2float(hv1->x), v.w - __half2float(hv1->y));
    reinterpret_cast<uint32_t*>(hi)[2*i]   = h0;
    reinterpret_cast<uint32_t*>(hi)[2*i+1] = h1;
    reinterpret_cast<uint32_t*>(lo)[2*i]   = l0;
    reinterpret_cast<uint32_t*>(lo)[2*i+1] = l1;
}

// =================================================================
// transpose + split: WT[n][k] = W[k][n], fp16 hi/lo
// =================================================================
__global__ __launch_bounds__(256) void splitT_kernel(
    const float* __restrict__ W, __half* __restrict__ hiT,
    __half* __restrict__ loT)
{
    __shared__ float tile[32][33];
    int n0 = blockIdx.x * 32, k0 = blockIdx.y * 32;
    int tx = threadIdx.x & 31, ty = threadIdx.x >> 5;
#pragma unroll
    for (int i = 0; i < 4; i++) {
        int kk = ty + i * 8;
        tile[kk][tx] = W[(size_t)(k0 + kk) * DD + n0 + tx];
    }
    __syncthreads();
#pragma unroll
    for (int i = 0; i < 4; i++) {
        int a = ty + i * 8;
        float v = tile[tx][a];
        __half h = __float2half(v);
        hiT[(size_t)(n0 + a) * DD + k0 + tx] = h;
        loT[(size_t)(n0 + a) * DD + k0 + tx] = __float2half(v - __half2float(h));
    }
}

// =================================================================
// HMMA fp16 GEMM, 128x128 tile, BK=32, NST-stage cp.async pipeline.
// PASSES 1: A single, B single ; PASSES 3: A hi/lo x B hi/lo
// MODE 0: per-warp top2(psq-2*dot) -> g_top2
// MODE 2: plain store, stride DD (PW)
// MODE 3: class-head fusion: stage C to smem, leaky(C+bias) . cw -> g_part
// =================================================================
template <int PASSES, int MODE, int NST>
__global__ __launch_bounds__(256)
void hmma_gemm_kernel(const __half* __restrict__ Ahi, const __half* __restrict__ Alo,
                      const __half* __restrict__ Bhi, const __half* __restrict__ Blo,
                      const float* __restrict__ bias, float* __restrict__ outp,
                      const float* __restrict__ cw)
{
    constexpr int TILES = (PASSES == 3) ? 4 : 2;
    constexpr int STB = TILES * 8192;
    constexpr int BOFF = (PASSES == 1) ? 8192 : 16384;
    constexpr int DEPTH = NST - 1;
    extern __shared__ char smem[];
    const uint32_t sb = smem_u32(smem);
    const int tid = threadIdx.x;
    const int lane = tid & 31;
    const int w = tid >> 5;
    const int wm = w & 3;
    const int wn = w >> 2;
    const int row0 = blockIdx.y * 128;
    const int col0 = blockIdx.x * 128;

    const int q  = lane >> 3;
    const int lr = lane & 7;
    const int achk = q >> 1;
    const int bchk = q & 1;
    int arow[2], brow[4];
#pragma unroll
    for (int mi = 0; mi < 2; mi++) arow[mi] = wm*32 + mi*16 + ((q & 1) << 3) + lr;
#pragma unroll
    for (int ng = 0; ng < 4; ng++) brow[ng] = wn*64 + ng*16 + ((q >> 1) << 3) + lr;

    float c[2][8][4];
#pragma unroll
    for (int mi = 0; mi < 2; mi++)
#pragma unroll
        for (int nf = 0; nf < 8; nf++)
#pragma unroll
            for (int j = 0; j < 4; j++) c[mi][nf][j] = 0.f;

    auto issue = [&](int st, int kt) {
        const int k0 = kt << 5;
        const uint32_t sbase = sb + st * STB;
#pragma unroll
        for (int it = 0; it < TILES * 2; it++) {
            int ch = it * 256 + tid;
            int t = ch >> 9;
            int within = ch & 511;
            int r = within >> 2, cc = within & 3;
            const __half* src;
            int rbase;
            if (PASSES == 1) {
                src = (t == 0) ? Ahi : Bhi;
                rbase = (t == 0) ? row0 : col0;
            } else {
                src = (t == 0) ? Ahi : (t == 1) ? Alo : (t == 2) ? Bhi : Blo;
                rbase = (t < 2) ? row0 : col0;
            }
            const void* g = src + (size_t)(rbase + r) * DD + k0 + cc * 8;
            uint32_t s = sbase + t * 8192 + r * 64 + ((cc ^ ((r >> 1) & 3)) << 4);
            asm volatile("cp.async.cg.shared.global [%0], [%1], 16;" :: "r"(s), "l"(g));
        }
        asm volatile("cp.async.commit_group;" ::: "memory");
    };

    auto compute = [&](int st) {
        const uint32_t sbase = sb + st * STB;
#pragma unroll
        for (int ks = 0; ks < 2; ks++) {
            uint32_t ah[2][4], al[2][4], bh[4][4], bl[4][4];
#pragma unroll
            for (int mi = 0; mi < 2; mi++) {
                uint32_t ra = sbase + arow[mi] * 64 +
                              ((((ks << 1) | achk) ^ ((arow[mi] >> 1) & 3)) << 4);
                ldsm4(ah[mi], ra);
                if (PASSES == 3) ldsm4(al[mi], ra + 8192);
            }
#pragma unroll
            for (int ng = 0; ng < 4; ng++) {
                uint32_t rb = sbase + BOFF + brow[ng] * 64 +
                              ((((ks << 1) | bchk) ^ ((brow[ng] >> 1) & 3)) << 4);
                ldsm4(bh[ng], rb);
                if (PASSES == 3) ldsm4(bl[ng], rb + 8192);
            }
#pragma unroll
            for (int mi = 0; mi < 2; mi++)
#pragma unroll
                for (int ng = 0; ng < 4; ng++)
#pragma unroll
                    for (int h = 0; h < 2; h++) {
                        int nf = ng * 2 + h;
                        mma16816(c[mi][nf], ah[mi], bh[ng][h*2], bh[ng][h*2+1]);
                        if (PASSES == 3) {
                            mma16816(c[mi][nf], ah[mi], bl[ng][h*2], bl[ng][h*2+1]);
                            mma16816(c[mi][nf], al[mi], bh[ng][h*2], bh[ng][h*2+1]);
                        }
                    }
        }
    };

    const int NK = DD / 32;
#pragma unroll
    for (int i = 0; i < DEPTH; i++) issue(i, i);
    for (int kt = 0; kt < NK; kt++) {
        const int rem = NK - 1 - kt;
        if (DEPTH == 3) {
            if (rem >= 2)      asm volatile("cp.async.wait_group 2;" ::: "memory");
            else if (rem == 1) asm volatile("cp.async.wait_group 1;" ::: "memory");
            else               asm volatile("cp.async.wait_group 0;" ::: "memory");
        } else {
            if (rem >= 1)      asm volatile("cp.async.wait_group 1;" ::: "memory");
            else               asm volatile("cp.async.wait_group 0;" ::: "memory");
        }
        __syncthreads();
        compute(kt % NST);
        if (kt + DEPTH < NK) issue((kt + DEPTH) % NST, kt + DEPTH);
        __syncthreads();
    }
    __syncthreads();

    if (MODE == 0) {
#pragma unroll
        for (int mi = 0; mi < 2; mi++)
#pragma unroll
            for (int rh = 0; rh < 2; rh++) {
                int lrow_ = wm*32 + mi*16 + rh*8 + (lane >> 2);
                float v1 = 3.4e38f, v2 = 3.4e38f;
                int i1 = 0, i2 = 0;
#pragma unroll
                for (int nf = 0; nf < 8; nf++) {
                    int col = col0 + wn*64 + nf*8 + ((lane & 3) << 1);
                    float s0 = bias[col]     - 2.f * c[mi][nf][rh*2];
                    float s1 = bias[col + 1] - 2.f * c[mi][nf][rh*2+1];
                    top2_upd(s0, col,     v1, i1, v2, i2);
                    top2_upd(s1, col + 1, v1, i1, v2, i2);
                }
#pragma unroll
                for (int d = 1; d <= 2; d <<= 1) {
                    float w1 = __shfl_xor_sync(0xffffffffu, v1, d);
                    float w2 = __shfl_xor_sync(0xffffffffu, v2, d);
                    int   j1 = __shfl_xor_sync(0xffffffffu, i1, d);
                    int   j2 = __shfl_xor_sync(0xffffffffu, i2, d);
                    top2_merge(w1, j1, w2, j2, v1, i1, v2, i2);
                }
                if ((lane & 3) == 0)
                    reinterpret_cast<float4*>(outp)[(size_t)(row0 + lrow_) * NCAND
                                                    + blockIdx.x * 2 + wn] =
                        make_float4(v1, __int_as_float(i1), v2, __int_as_float(i2));
            }
    } else if (MODE == 2) {
#pragma unroll
        for (int mi = 0; mi < 2; mi++)
#pragma unroll
            for (int rh = 0; rh < 2; rh++) {
                int r = row0 + wm*32 + mi*16 + rh*8 + (lane >> 2);
#pragma unroll
                for (int nf = 0; nf < 8; nf++) {
                    int col = col0 + wn*64 + nf*8 + ((lane & 3) << 1);
                    float2 o = {c[mi][nf][rh*2], c[mi][nf][rh*2+1]};
                    *reinterpret_cast<float2*>(&outp[(size_t)r * DD + col]) = o;
                }
            }
    } else {
        // MODE 3: stage C to smem (stride 133, conflict-free), then
        // class-head partial (row-per-thread, k-half split, cws broadcast).
        float* cbuf = reinterpret_cast<float*>(smem);                  // [128][133]
        float* cwsm = cbuf + 128 * 133;                                // [128][26]
        float* bsm  = cwsm + 128 * 26;                                 // [128]
        float* red  = bsm + 128;                                       // [128][26]
#pragma unroll
        for (int mi = 0; mi < 2; mi++)
#pragma unroll
            for (int rh = 0; rh < 2; rh++) {
                int r = wm*32 + mi*16 + rh*8 + (lane >> 2);
#pragma unroll
                for (int nf = 0; nf < 8; nf++) {
                    int cl = wn*64 + nf*8 + ((lane & 3) << 1);
                    cbuf[r * 133 + cl]     = c[mi][nf][rh*2];
                    cbuf[r * 133 + cl + 1] = c[mi][nf][rh*2+1];
                }
            }
        // enumerate all (cl 0..127, o 0..31) pairs: bound must be 128*32
        for (int i = tid; i < 128 * 32; i += 256) {
            int cl = i >> 5;
            int o = i & 31;
            if (o < OUTC) cwsm[cl * 26 + o] = cw[(size_t)o * PP + col0 + cl];
        }
        if (tid < 128) bsm[tid] = bias[col0 + tid];
        __syncthreads();

        const int row = tid & 127;
        const int kh = tid >> 7;
        float acc[OUTC];
#pragma unroll
        for (int o = 0; o < OUTC; o++) acc[o] = 0.f;
#pragma unroll 4
        for (int kk = 0; kk < 64; kk++) {
            int cl = kh * 64 + kk;
            float v = cbuf[row * 133 + cl] + bsm[cl];
            v = v > 0.f ? v : 0.01f * v;
#pragma unroll
            for (int o = 0; o < OUTC; o++)
                acc[o] = fmaf(v, cwsm[cl * 26 + o], acc[o]);
        }
        if (kh == 1) {
#pragma unroll
            for (int o = 0; o < OUTC; o++) red[row * 26 + o] = acc[o];
        }
        __syncthreads();
        if (kh == 0) {
            float* dst = outp + ((size_t)blockIdx.x * BB + row0 + row) * OUTC;
#pragma unroll
            for (int o = 0; o < OUTC; o++)
                dst[o] = acc[o] + red[row * 26 + o];
        }
    }
}

// =================================================================
// reduce class partials: out[b][o] = sum_t part[t][b][o] + cb[o]
// =================================================================
__global__ __launch_bounds__(256)
void reduce_class_kernel(const float* __restrict__ cb, float* __restrict__ out)
{
    int i = blockIdx.x * 256 + threadIdx.x;
    if (i >= BB * OUTC) return;
    int o = i % OUTC;
    float s = cb[o];
#pragma unroll
    for (int t = 0; t < 8; t++)
        s += g_part[(size_t)t * BB * OUTC + i];
    out[i] = s;
}

// =================================================================
// 32 candidates/row; exact fp64 rescue over all within MARGIN
// =================================================================
__global__ __launch_bounds__(256)
void argmin_reduce_kernel(const float* __restrict__ patient, const float* __restrict__ protos)
{
    int w = (blockIdx.x * 256 + threadIdx.x) >> 5;
    int lane = threadIdx.x & 31;
    if (w >= BB) return;

    float4 qd = g_top2[(size_t)w * NCAND + (lane >> 1)];
    float val;
    int idx;
    if (lane & 1) { val = qd.z; idx = __float_as_int(qd.w); }
    else          { val = qd.x; idx = __float_as_int(qd.y); }

    float vmin = val;
#pragma unroll
    for (int d = 16; d; d >>= 1)
        vmin = fminf(vmin, __shfl_xor_sync(0xffffffffu, vmin, d));

    bool flag = (val < vmin + MARGIN);
    unsigned mask = __ballot_sync(0xffffffffu, flag);

    if (__popc(mask) == 1) {
        if (flag) g_labels[w] = idx;
        return;
    }

    const float* x = patient + (size_t)w * DD;
    double bestd = 1.0e300;
    int besti = 0x7FFFFFFF;
    while (mask) {
        int src = __ffs(mask) - 1;
        mask &= mask - 1;
        int ci = __shfl_sync(0xffffffffu, idx, src);
        const float* pr = protos + (size_t)ci * DD;
        double acc = 0.0;
        for (int k = lane; k < DD; k += 32)
            acc += (double)x[k] * (double)pr[k];
#pragma unroll
        for (int d = 16; d; d >>= 1)
            acc += __shfl_down_sync(0xffffffffu, acc, d);
        if (lane == 0) {
            double d2 = (double)g_psq[ci] - 2.0 * acc;
            if (d2 < bestd || (d2 == bestd && ci < besti)) { bestd = d2; besti = ci; }
        }
    }
    if (lane == 0) g_labels[w] = besti;
}

// =================================================================
// lam[b] = sigmoid(PW[la].protos[lb] + bil_b + v1[la] + v2[lb])
// =================================================================
__global__ __launch_bounds__(256)
void lam_kernel(const int* __restrict__ index, const float* __restrict__ bilinear_b,
                const float* __restrict__ protos)
{
    int w = (blockIdx.x * 256 + threadIdx.x) >> 5;
    int lane = threadIdx.x & 31;
    if (w >= BB) return;
    int la = g_labels[w];
    int lb = g_labels[index[w]];
    const float4* a = reinterpret_cast<const float4*>(g_PW + (size_t)la * DD);
    const float4* p = reinterpret_cast<const float4*>(protos + (size_t)lb * DD);
    float acc = 0.f;
    for (int k = lane; k < DD / 4; k += 32) {
        float4 u = a[k], v = p[k];
        acc = fmaf(u.x, v.x, acc); acc = fmaf(u.y, v.y, acc);
        acc = fmaf(u.z, v.z, acc); acc = fmaf(u.w, v.w, acc);
    }
#pragma unroll
    for (int off = 16; off; off >>= 1) acc += __shfl_down_sync(0xffffffffu, acc, off);
    if (lane == 0) {
        float s = acc + bilinear_b[0] + g_v1[la] + g_v2[lb];
        g_lam[w] = 1.f / (1.f + expf(-s));
    }
}

// =================================================================
// mixed = lam*x + (1-lam)*x[index]; emit fp16 (hi only)
// =================================================================
__global__ __launch_bounds__(256)
void mix_kernel(const float* __restrict__ patient, const int* __restrict__ index)
{
    int b = blockIdx.x;
    float lam = g_lam[b], oml = 1.f - lam;
    int ib = index[b];
    int t = threadIdx.x;
    float4 a = reinterpret_cast<const float4*>(patient + (size_t)b * DD)[t];
    float4 c = reinterpret_cast<const float4*>(patient + (size_t)ib * DD)[t];
    float m0 = lam * a.x + oml * c.x, m1 = lam * a.y + oml * c.y;
    float m2 = lam * a.z + oml * c.z, m3 = lam * a.w + oml * c.w;
    size_t o = (size_t)b * (DD / 2) + 2 * t;
    reinterpret_cast<uint32_t*>(g_mx_hi)[o]     = pk2h(m0, m1);
    reinterpret_cast<uint32_t*>(g_mx_hi)[o + 1] = pk2h(m2, m3);
}

// =================================================================
// launch
// =================================================================
extern "C" void kernel_launch(void* const* d_in, const int* in_sizes, int n_in,
                              void* d_out, int out_size)
{
    const float* patient    = (const float*)d_in[0];
    const float* protos     = (const float*)d_in[1];
    const int*   index      = (const int*)  d_in[2];
    const float* bilinear_w = (const float*)d_in[3];
    const float* bilinear_b = (const float*)d_in[4];
    const float* lin_w      = (const float*)d_in[5];
    const float* proto_fc_w = (const float*)d_in[6];
    const float* proto_fc_b = (const float*)d_in[7];
    const float* class_fc_w = (const float*)d_in[8];
    const float* class_fc_b = (const float*)d_in[9];
    float* out = (float*)d_out;

    float *pPW, *pPsq, *pPart;
    float4* pTop2;
    __half *pPaHi, *pPrHi, *pPrLo, *pFcHi, *pWtHi, *pWtLo, *pMxHi;
    cudaGetSymbolAddress((void**)&pPW, g_PW);
    cudaGetSymbolAddress((void**)&pPsq, g_psq);
    cudaGetSymbolAddress((void**)&pPart, g_part);
    cudaGetSymbolAddress((void**)&pTop2, g_top2);
    cudaGetSymbolAddress((void**)&pPaHi, g_pa_hi);
    cudaGetSymbolAddress((void**)&pPrHi, g_pr_hi);
    cudaGetSymbolAddress((void**)&pPrLo, g_pr_lo);
    cudaGetSymbolAddress((void**)&pFcHi, g_fc_hi);
    cudaGetSymbolAddress((void**)&pWtHi, g_wt_hi);
    cudaGetSymbolAddress((void**)&pWtLo, g_wt_lo);
    cudaGetSymbolAddress((void**)&pMxHi, g_mx_hi);

    const int SM1   = 4 * 2 * 8192 + 4096;                         // 69632 (dist)
    const int SM3   = 3 * 4 * 8192 + 4096;                         // 102400 (PW)
    const int SMCLS = (128*133 + 128*26 + 128 + 128*26) * 4;       // 95232 (logits+class)
    const int SMLOG = (SM1 > SMCLS) ? SM1 : SMCLS;
    cudaFuncSetAttribute(hmma_gemm_kernel<1,0,4>, cudaFuncAttributeMaxDynamicSharedMemorySize, SM1);
    cudaFuncSetAttribute(hmma_gemm_kernel<1,3,4>, cudaFuncAttributeMaxDynamicSharedMemorySize, SMLOG);
    cudaFuncSetAttribute(hmma_gemm_kernel<3,2,3>, cudaFuncAttributeMaxDynamicSharedMemorySize, SM3);

    prep_kernel<<<PP, 256>>>(protos, lin_w);

    convert_kernel<<<(BB * DD / 4) / 256, 256>>>(patient, pPaHi, BB * DD / 4);
    split_kernel<<<(PP * DD / 4) / 256, 256>>>(protos, pPrHi, pPrLo, PP * DD / 4);
    convert_kernel<<<(PP * DD / 4) / 256, 256>>>(proto_fc_w, pFcHi, PP * DD / 4);
    splitT_kernel<<<dim3(32, 32), 256>>>(bilinear_w, pWtHi, pWtLo);

    // PW = protos @ W  (3-pass: lam path stays accurate)
    hmma_gemm_kernel<3,2,3><<<dim3(DD / 128, PP / 128), 256, SM3>>>(
        pPrHi, pPrLo, pWtHi, pWtLo, nullptr, pPW, nullptr);

    // distance GEMM (1-pass fp16, deep pipeline) + per-warp top2 candidates
    hmma_gemm_kernel<1,0,4><<<dim3(PP / 128, BB / 128), 256, SM1>>>(
        pPaHi, nullptr, pPrHi, nullptr, pPsq, (float*)pTop2, nullptr);

    argmin_reduce_kernel<<<BB / 8, 256>>>(patient, protos);

    lam_kernel<<<BB / 8, 256>>>(index, bilinear_b, protos);

    mix_kernel<<<BB, 256>>>(patient, index);

    // logits GEMM (1-pass) with smem-staged fused class-head partial epilogue
    hmma_gemm_kernel<1,3,4><<<dim3(PP / 128, BB / 128), 256, SMLOG>>>(
        pMxHi, nullptr, pFcHi, nullptr, proto_fc_b, pPart, class_fc_w);

    reduce_class_kernel<<<(BB * OUTC + 255) / 256, 256>>>(class_fc_b, out);
}

// round 13
// speedup vs baseline: 1.4260x; 1.0765x over previous
#include <cuda_runtime.h>
#include <cuda_fp16.h>
#include <math.h>
#include <stdint.h>

#define BB   16384
#define DD   1024
#define PP   1024
#define OUTC 25
#define NCAND 16            // float4 slots per row (2 candidates each = 32)
#define MARGIN 0.35f

// ---------------- device scratch ----------------
__device__ float g_psq[PP];
__device__ float g_v1[PP];
__device__ float g_v2[PP];
__device__ float g_PW[PP * DD];
__device__ float g_PWpart[(size_t)4 * PP * DD];   // split-K partials
__device__ int   g_labels[BB];
__device__ float g_lam[BB];
__device__ float4 g_top2[(size_t)BB * NCAND];
__device__ float g_part[(size_t)8 * BB * OUTC];   // class-head partials (per col-tile)

__device__ __half g_pa_hi[(size_t)BB * DD];
__device__ __half g_pr_hi[(size_t)PP * DD];
__device__ __half g_pr_lo[(size_t)PP * DD];
__device__ __half g_fc_hi[(size_t)PP * DD];
__device__ __half g_wt_hi[(size_t)DD * DD];
__device__ __half g_wt_lo[(size_t)DD * DD];
__device__ __half g_mx_hi[(size_t)BB * DD];

// ---------------- helpers ----------------
__device__ __forceinline__ uint32_t smem_u32(const void* p) {
    uint32_t a;
    asm("{ .reg .u64 t; cvta.to.shared.u64 t, %1; cvt.u32.u64 %0, t; }" : "=r"(a) : "l"(p));
    return a;
}
__device__ __forceinline__ void ldsm4(uint32_t r[4], uint32_t addr) {
    asm volatile("ldmatrix.sync.aligned.m8n8.x4.shared.b16 {%0,%1,%2,%3}, [%4];"
                 : "=r"(r[0]), "=r"(r[1]), "=r"(r[2]), "=r"(r[3]) : "r"(addr));
}
__device__ __forceinline__ void mma16816(float c[4], const uint32_t a[4],
                                         uint32_t b0, uint32_t b1) {
    asm volatile("mma.sync.aligned.m16n8k16.row.col.f32.f16.f16.f32 "
                 "{%0,%1,%2,%3}, {%4,%5,%6,%7}, {%8,%9}, {%0,%1,%2,%3};"
                 : "+f"(c[0]), "+f"(c[1]), "+f"(c[2]), "+f"(c[3])
                 : "r"(a[0]), "r"(a[1]), "r"(a[2]), "r"(a[3]), "r"(b0), "r"(b1));
}
__device__ __forceinline__ uint32_t pk2h(float a, float b) {
    __half2 t;
    t.x = __float2half(a); t.y = __float2half(b);
    return *reinterpret_cast<uint32_t*>(&t);
}
__device__ __forceinline__ void top2_upd(float s, int idx, float& v1, int& i1,
                                         float& v2, int& i2) {
    if (s < v1 || (s == v1 && idx < i1)) { v2 = v1; i2 = i1; v1 = s; i1 = idx; }
    else if (s < v2 || (s == v2 && idx < i2)) { v2 = s; i2 = idx; }
}
__device__ __forceinline__ void top2_merge(float w1, int j1, float w2, int j2,
                                           float& v1, int& i1, float& v2, int& i2) {
    top2_upd(w1, j1, v1, i1, v2, i2);
    top2_upd(w2, j2, v1, i1, v2, i2);
}

// =================================================================
// prep: p_sq, v1, v2
// =================================================================
__global__ __launch_bounds__(256) void prep_kernel(
    const float* __restrict__ protos, const float* __restrict__ lin_w)
{
    int p = blockIdx.x, t = threadIdx.x;
    float sq = 0.f, a1 = 0.f, a2 = 0.f;
    const float* row = protos + (size_t)p * DD;
    for (int k = t; k < DD; k += 256) {
        float v = row[k];
        sq = fmaf(v, v, sq);
        a1 = fmaf(v, lin_w[k], a1);
        a2 = fmaf(v, lin_w[DD + k], a2);
    }
    __shared__ float s1[256], s2[256], s3[256];
    s1[t] = sq; s2[t] = a1; s3[t] = a2;
    __syncthreads();
    for (int off = 128; off; off >>= 1) {
        if (t < off) { s1[t] += s1[t+off]; s2[t] += s2[t+off]; s3[t] += s3[t+off]; }
        __syncthreads();
    }
    if (t == 0) { g_psq[p] = s1[0]; g_v1[p] = s2[0]; g_v2[p] = s3[0]; }
}

// =================================================================
// convert fp32 -> fp16 (hi only)
// =================================================================
__global__ __launch_bounds__(256) void convert_kernel(
    const float* __restrict__ src, __half* __restrict__ hi, int n4)
{
    int i = blockIdx.x * 256 + threadIdx.x;
    if (i >= n4) return;
    float4 v = reinterpret_cast<const float4*>(src)[i];
    reinterpret_cast<uint32_t*>(hi)[2*i]   = pk2h(v.x, v.y);
    reinterpret_cast<uint32_t*>(hi)[2*i+1] = pk2h(v.z, v.w);
}

// =================================================================
// split fp32 -> fp16 hi + lo
// =================================================================
__global__ __launch_bounds__(256) void split_kernel(
    const float* __restrict__ src, __half* __restrict__ hi,
    __half* __restrict__ lo, int n4)
{
    int i = blockIdx.x * 256 + threadIdx.x;
    if (i >= n4) return;
    float4 v = reinterpret_cast<const float4*>(src)[i];
    uint32_t h0 = pk2h(v.x, v.y), h1 = pk2h(v.z, v.w);
    __half2* hv0 = reinterpret_cast<__half2*>(&h0);
    __half2* hv1 = reinterpret_cast<__half2*>(&h1);
    uint32_t l0 = pk2h(v.x - __half2float(hv0->x), v.y - __half2float(hv0->y));
    uint32_t l1 = pk2h(v.z - __half2float(hv1->x), v.w - __half2float(hv1->y));
    reinterpret_cast<uint32_t*>(hi)[2*i]   = h0;
    reinterpret_cast<uint32_t*>(hi)[2*i+1] = h1;
    reinterpret_cast<uint32_t*>(lo)[2*i]   = l0;
    reinterpret_cast<uint32_t*>(lo)[2*i+1] = l1;
}

// =================================================================
// transpose + split: WT[n][k] = W[k][n], fp16 hi/lo
// =================================================================
__global__ __launch_bounds__(256) void splitT_kernel(
    const float* __restrict__ W, __half* __restrict__ hiT,
    __half* __restrict__ loT)
{
    __shared__ float tile[32][33];
    int n0 = blockIdx.x * 32, k0 = blockIdx.y * 32;
    int tx = threadIdx.x & 31, ty = threadIdx.x >> 5;
#pragma unroll
    for (int i = 0; i < 4; i++) {
        int kk = ty + i * 8;
        tile[kk][tx] = W[(size_t)(k0 + kk) * DD + n0 + tx];
    }
    __syncthreads();
#pragma unroll
    for (int i = 0; i < 4; i++) {
        int a = ty + i * 8;
        float v = tile[tx][a];
        __half h = __float2half(v);
        hiT[(size_t)(n0 + a) * DD + k0 + tx] = h;
        loT[(size_t)(n0 + a) * DD + k0 + tx] = __float2half(v - __half2float(h));
    }
}

// =================================================================
// HMMA fp16 GEMM, 128x128 tile, BK=32, NST-stage cp.async pipeline.
// K range = [kbase*32, (kbase+nkIter)*32); MODE 2 adds blockIdx.z*nkIter
// PASSES 1: A single, B single ; PASSES 3: A hi/lo x B hi/lo
// MODE 0: per-warp top2(psq-2*dot) -> g_top2
// MODE 2: partial store -> outp + blockIdx.z*PP*DD, stride DD (PW split-K)
// MODE 3: class-head fusion: stage C to smem, leaky(C+bias) . cw -> g_part
// =================================================================
template <int PASSES, int MODE, int NST>
__global__ __launch_bounds__(256)
void hmma_gemm_kernel(const __half* __restrict__ Ahi, const __half* __restrict__ Alo,
                      const __half* __restrict__ Bhi, const __half* __restrict__ Blo,
                      const float* __restrict__ bias, float* __restrict__ outp,
                      const float* __restrict__ cw, int kbase, int nkIter)
{
    constexpr int TILES = (PASSES == 3) ? 4 : 2;
    constexpr int STB = TILES * 8192;
    constexpr int BOFF = (PASSES == 1) ? 8192 : 16384;
    constexpr int DEPTH = NST - 1;
    extern __shared__ char smem[];
    const uint32_t sb = smem_u32(smem);
    const int tid = threadIdx.x;
    const int lane = tid & 31;
    const int w = tid >> 5;
    const int wm = w & 3;
    const int wn = w >> 2;
    const int row0 = blockIdx.y * 128;
    const int col0 = blockIdx.x * 128;

    if (MODE == 2) kbase += blockIdx.z * nkIter;   // split-K: per-z K offset

    const int q  = lane >> 3;
    const int lr = lane & 7;
    const int achk = q >> 1;
    const int bchk = q & 1;
    int arow[2], brow[4];
#pragma unroll
    for (int mi = 0; mi < 2; mi++) arow[mi] = wm*32 + mi*16 + ((q & 1) << 3) + lr;
#pragma unroll
    for (int ng = 0; ng < 4; ng++) brow[ng] = wn*64 + ng*16 + ((q >> 1) << 3) + lr;

    float c[2][8][4];
#pragma unroll
    for (int mi = 0; mi < 2; mi++)
#pragma unroll
        for (int nf = 0; nf < 8; nf++)
#pragma unroll
            for (int j = 0; j < 4; j++) c[mi][nf][j] = 0.f;

    auto issue = [&](int st, int kt) {
        const int k0 = (kbase + kt) << 5;
        const uint32_t sbase = sb + st * STB;
#pragma unroll
        for (int it = 0; it < TILES * 2; it++) {
            int ch = it * 256 + tid;
            int t = ch >> 9;
            int within = ch & 511;
            int r = within >> 2, cc = within & 3;
            const __half* src;
            int rbase;
            if (PASSES == 1) {
                src = (t == 0) ? Ahi : Bhi;
                rbase = (t == 0) ? row0 : col0;
            } else {
                src = (t == 0) ? Ahi : (t == 1) ? Alo : (t == 2) ? Bhi : Blo;
                rbase = (t < 2) ? row0 : col0;
            }
            const void* g = src + (size_t)(rbase + r) * DD + k0 + cc * 8;
            uint32_t s = sbase + t * 8192 + r * 64 + ((cc ^ ((r >> 1) & 3)) << 4);
            asm volatile("cp.async.cg.shared.global [%0], [%1], 16;" :: "r"(s), "l"(g));
        }
        asm volatile("cp.async.commit_group;" ::: "memory");
    };

    auto compute = [&](int st) {
        const uint32_t sbase = sb + st * STB;
#pragma unroll
        for (int ks = 0; ks < 2; ks++) {
            uint32_t ah[2][4], al[2][4], bh[4][4], bl[4][4];
#pragma unroll
            for (int mi = 0; mi < 2; mi++) {
                uint32_t ra = sbase + arow[mi] * 64 +
                              ((((ks << 1) | achk) ^ ((arow[mi] >> 1) & 3)) << 4);
                ldsm4(ah[mi], ra);
                if (PASSES == 3) ldsm4(al[mi], ra + 8192);
            }
#pragma unroll
            for (int ng = 0; ng < 4; ng++) {
                uint32_t rb = sbase + BOFF + brow[ng] * 64 +
                              ((((ks << 1) | bchk) ^ ((brow[ng] >> 1) & 3)) << 4);
                ldsm4(bh[ng], rb);
                if (PASSES == 3) ldsm4(bl[ng], rb + 8192);
            }
#pragma unroll
            for (int mi = 0; mi < 2; mi++)
#pragma unroll
                for (int ng = 0; ng < 4; ng++)
#pragma unroll
                    for (int h = 0; h < 2; h++) {
                        int nf = ng * 2 + h;
                        mma16816(c[mi][nf], ah[mi], bh[ng][h*2], bh[ng][h*2+1]);
                        if (PASSES == 3) {
                            mma16816(c[mi][nf], ah[mi], bl[ng][h*2], bl[ng][h*2+1]);
                            mma16816(c[mi][nf], al[mi], bh[ng][h*2], bh[ng][h*2+1]);
                        }
                    }
        }
    };

    const int NK = nkIter;
#pragma unroll
    for (int i = 0; i < DEPTH; i++) issue(i, i);
    for (int kt = 0; kt < NK; kt++) {
        const int rem = NK - 1 - kt;
        if (DEPTH == 3) {
            if (rem >= 2)      asm volatile("cp.async.wait_group 2;" ::: "memory");
            else if (rem == 1) asm volatile("cp.async.wait_group 1;" ::: "memory");
            else               asm volatile("cp.async.wait_group 0;" ::: "memory");
        } else {
            if (rem >= 1)      asm volatile("cp.async.wait_group 1;" ::: "memory");
            else               asm volatile("cp.async.wait_group 0;" ::: "memory");
        }
        __syncthreads();
        compute(kt % NST);
        if (kt + DEPTH < NK) issue((kt + DEPTH) % NST, kt + DEPTH);
        __syncthreads();
    }
    __syncthreads();

    if (MODE == 0) {
#pragma unroll
        for (int mi = 0; mi < 2; mi++)
#pragma unroll
            for (int rh = 0; rh < 2; rh++) {
                int lrow_ = wm*32 + mi*16 + rh*8 + (lane >> 2);
                float v1 = 3.4e38f, v2 = 3.4e38f;
                int i1 = 0, i2 = 0;
#pragma unroll
                for (int nf = 0; nf < 8; nf++) {
                    int col = col0 + wn*64 + nf*8 + ((lane & 3) << 1);
                    float s0 = bias[col]     - 2.f * c[mi][nf][rh*2];
                    float s1 = bias[col + 1] - 2.f * c[mi][nf][rh*2+1];
                    top2_upd(s0, col,     v1, i1, v2, i2);
                    top2_upd(s1, col + 1, v1, i1, v2, i2);
                }
#pragma unroll
                for (int d = 1; d <= 2; d <<= 1) {
                    float w1 = __shfl_xor_sync(0xffffffffu, v1, d);
                    float w2 = __shfl_xor_sync(0xffffffffu, v2, d);
                    int   j1 = __shfl_xor_sync(0xffffffffu, i1, d);
                    int   j2 = __shfl_xor_sync(0xffffffffu, i2, d);
                    top2_merge(w1, j1, w2, j2, v1, i1, v2, i2);
                }
                if ((lane & 3) == 0)
                    reinterpret_cast<float4*>(outp)[(size_t)(row0 + lrow_) * NCAND
                                                    + blockIdx.x * 2 + wn] =
                        make_float4(v1, __int_as_float(i1), v2, __int_as_float(i2));
            }
    } else if (MODE == 2) {
        float* dstp = outp + (size_t)blockIdx.z * PP * DD;
#pragma unroll
        for (int mi = 0; mi < 2; mi++)
#pragma unroll
            for (int rh = 0; rh < 2; rh++) {
                int r = row0 + wm*32 + mi*16 + rh*8 + (lane >> 2);
#pragma unroll
                for (int nf = 0; nf < 8; nf++) {
                    int col = col0 + wn*64 + nf*8 + ((lane & 3) << 1);
                    float2 o = {c[mi][nf][rh*2], c[mi][nf][rh*2+1]};
                    *reinterpret_cast<float2*>(&dstp[(size_t)r * DD + col]) = o;
                }
            }
    } else {
        // MODE 3: stage C to smem (stride 133), then class-head partial.
        float* cbuf = reinterpret_cast<float*>(smem);                  // [128][133]
        float* cwsm = cbuf + 128 * 133;                                // [128][26]
        float* bsm  = cwsm + 128 * 26;                                 // [128]
        float* red  = bsm + 128;                                       // [128][26]
#pragma unroll
        for (int mi = 0; mi < 2; mi++)
#pragma unroll
            for (int rh = 0; rh < 2; rh++) {
                int r = wm*32 + mi*16 + rh*8 + (lane >> 2);
#pragma unroll
                for (int nf = 0; nf < 8; nf++) {
                    int cl = wn*64 + nf*8 + ((lane & 3) << 1);
                    cbuf[r * 133 + cl]     = c[mi][nf][rh*2];
                    cbuf[r * 133 + cl + 1] = c[mi][nf][rh*2+1];
                }
            }
        for (int i = tid; i < 128 * 32; i += 256) {
            int cl = i >> 5;
            int o = i & 31;
            if (o < OUTC) cwsm[cl * 26 + o] = cw[(size_t)o * PP + col0 + cl];
        }
        if (tid < 128) bsm[tid] = bias[col0 + tid];
        __syncthreads();

        const int row = tid & 127;
        const int kh = tid >> 7;
        float acc[OUTC];
#pragma unroll
        for (int o = 0; o < OUTC; o++) acc[o] = 0.f;
#pragma unroll 4
        for (int kk = 0; kk < 64; kk++) {
            int cl = kh * 64 + kk;
            float v = cbuf[row * 133 + cl] + bsm[cl];
            v = v > 0.f ? v : 0.01f * v;
#pragma unroll
            for (int o = 0; o < OUTC; o++)
                acc[o] = fmaf(v, cwsm[cl * 26 + o], acc[o]);
        }
        if (kh == 1) {
#pragma unroll
            for (int o = 0; o < OUTC; o++) red[row * 26 + o] = acc[o];
        }
        __syncthreads();
        if (kh == 0) {
            float* dst = outp + ((size_t)blockIdx.x * BB + row0 + row) * OUTC;
#pragma unroll
            for (int o = 0; o < OUTC; o++)
                dst[o] = acc[o] + red[row * 26 + o];
        }
    }
}

// =================================================================
// reduce PW split-K partials (float4 vectorized)
// =================================================================
__global__ __launch_bounds__(256)
void reduce_pw_kernel()
{
    int i = blockIdx.x * 256 + threadIdx.x;     // over PP*DD/4
    const float4* p0 = reinterpret_cast<const float4*>(g_PWpart);
    const size_t stride = (size_t)PP * DD / 4;
    float4 a = p0[i];
    float4 b = p0[i + stride];
    float4 c = p0[i + 2 * stride];
    float4 d = p0[i + 3 * stride];
    float4 s;
    s.x = (a.x + b.x) + (c.x + d.x);
    s.y = (a.y + b.y) + (c.y + d.y);
    s.z = (a.z + b.z) + (c.z + d.z);
    s.w = (a.w + b.w) + (c.w + d.w);
    reinterpret_cast<float4*>(g_PW)[i] = s;
}

// =================================================================
// reduce class partials: out[b][o] = sum_t part[t][b][o] + cb[o]
// =================================================================
__global__ __launch_bounds__(256)
void reduce_class_kernel(const float* __restrict__ cb, float* __restrict__ out)
{
    int i = blockIdx.x * 256 + threadIdx.x;
    if (i >= BB * OUTC) return;
    int o = i % OUTC;
    float s = cb[o];
#pragma unroll
    for (int t = 0; t < 8; t++)
        s += g_part[(size_t)t * BB * OUTC + i];
    out[i] = s;
}

// =================================================================
// 32 candidates/row; exact fp64 rescue over all within MARGIN
// =================================================================
__global__ __launch_bounds__(256)
void argmin_reduce_kernel(const float* __restrict__ patient, const float* __restrict__ protos)
{
    int w = (blockIdx.x * 256 + threadIdx.x) >> 5;
    int lane = threadIdx.x & 31;
    if (w >= BB) return;

    float4 qd = g_top2[(size_t)w * NCAND + (lane >> 1)];
    float val;
    int idx;
    if (lane & 1) { val = qd.z; idx = __float_as_int(qd.w); }
    else          { val = qd.x; idx = __float_as_int(qd.y); }

    float vmin = val;
#pragma unroll
    for (int d = 16; d; d >>= 1)
        vmin = fminf(vmin, __shfl_xor_sync(0xffffffffu, vmin, d));

    bool flag = (val < vmin + MARGIN);
    unsigned mask = __ballot_sync(0xffffffffu, flag);

    if (__popc(mask) == 1) {
        if (flag) g_labels[w] = idx;
        return;
    }

    const float* x = patient + (size_t)w * DD;
    double bestd = 1.0e300;
    int besti = 0x7FFFFFFF;
    while (mask) {
        int src = __ffs(mask) - 1;
        mask &= mask - 1;
        int ci = __shfl_sync(0xffffffffu, idx, src);
        const float* pr = protos + (size_t)ci * DD;
        double acc = 0.0;
        for (int k = lane; k < DD; k += 32)
            acc += (double)x[k] * (double)pr[k];
#pragma unroll
        for (int d = 16; d; d >>= 1)
            acc += __shfl_down_sync(0xffffffffu, acc, d);
        if (lane == 0) {
            double d2 = (double)g_psq[ci] - 2.0 * acc;
            if (d2 < bestd || (d2 == bestd && ci < besti)) { bestd = d2; besti = ci; }
        }
    }
    if (lane == 0) g_labels[w] = besti;
}

// =================================================================
// lam[b] = sigmoid(PW[la].protos[lb] + bil_b + v1[la] + v2[lb])
// =================================================================
__global__ __launch_bounds__(256)
void lam_kernel(const int* __restrict__ index, const float* __restrict__ bilinear_b,
                const float* __restrict__ protos)
{
    int w = (blockIdx.x * 256 + threadIdx.x) >> 5;
    int lane = threadIdx.x & 31;
    if (w >= BB) return;
    int la = g_labels[w];
    int lb = g_labels[index[w]];
    const float4* a = reinterpret_cast<const float4*>(g_PW + (size_t)la * DD);
    const float4* p = reinterpret_cast<const float4*>(protos + (size_t)lb * DD);
    float acc = 0.f;
    for (int k = lane; k < DD / 4; k += 32) {
        float4 u = a[k], v = p[k];
        acc = fmaf(u.x, v.x, acc); acc = fmaf(u.y, v.y, acc);
        acc = fmaf(u.z, v.z, acc); acc = fmaf(u.w, v.w, acc);
    }
#pragma unroll
    for (int off = 16; off; off >>= 1) acc += __shfl_down_sync(0xffffffffu, acc, off);
    if (lane == 0) {
        float s = acc + bilinear_b[0] + g_v1[la] + g_v2[lb];
        g_lam[w] = 1.f / (1.f + expf(-s));
    }
}

// =================================================================
// mixed = lam*x + (1-lam)*x[index], from fp16 pa_hi; emit fp16
// =================================================================
__global__ __launch_bounds__(256)
void mix_kernel(const int* __restrict__ index)
{
    int b = blockIdx.x;
    float lam = g_lam[b], oml = 1.f - lam;
    int ib = index[b];
    int t = threadIdx.x;   // 256 threads * 4 halves (uint2) = 1024
    uint2 av = reinterpret_cast<const uint2*>(g_pa_hi + (size_t)b * DD)[t];
    uint2 cv = reinterpret_cast<const uint2*>(g_pa_hi + (size_t)ib * DD)[t];
    __half2 a0 = *reinterpret_cast<__half2*>(&av.x);
    __half2 a1 = *reinterpret_cast<__half2*>(&av.y);
    __half2 c0 = *reinterpret_cast<__half2*>(&cv.x);
    __half2 c1 = *reinterpret_cast<__half2*>(&cv.y);
    float m0 = lam * __half2float(a0.x) + oml * __half2float(c0.x);
    float m1 = lam * __half2float(a0.y) + oml * __half2float(c0.y);
    float m2 = lam * __half2float(a1.x) + oml * __half2float(c1.x);
    float m3 = lam * __half2float(a1.y) + oml * __half2float(c1.y);
    uint2 o;
    o.x = pk2h(m0, m1);
    o.y = pk2h(m2, m3);
    reinterpret_cast<uint2*>(g_mx_hi + (size_t)b * DD)[t] = o;
}

// =================================================================
// launch
// =================================================================
extern "C" void kernel_launch(void* const* d_in, const int* in_sizes, int n_in,
                              void* d_out, int out_size)
{
    const float* patient    = (const float*)d_in[0];
    const float* protos     = (const float*)d_in[1];
    const int*   index      = (const int*)  d_in[2];
    const float* bilinear_w = (const float*)d_in[3];
    const float* bilinear_b = (const float*)d_in[4];
    const float* lin_w      = (const float*)d_in[5];
    const float* proto_fc_w = (const float*)d_in[6];
    const float* proto_fc_b = (const float*)d_in[7];
    const float* class_fc_w = (const float*)d_in[8];
    const float* class_fc_b = (const float*)d_in[9];
    float* out = (float*)d_out;

    float *pPsq, *pPart, *pPWpart;
    float4* pTop2;
    __half *pPaHi, *pPrHi, *pPrLo, *pFcHi, *pWtHi, *pWtLo, *pMxHi;
    cudaGetSymbolAddress((void**)&pPsq, g_psq);
    cudaGetSymbolAddress((void**)&pPart, g_part);
    cudaGetSymbolAddress((void**)&pPWpart, g_PWpart);
    cudaGetSymbolAddress((void**)&pTop2, g_top2);
    cudaGetSymbolAddress((void**)&pPaHi, g_pa_hi);
    cudaGetSymbolAddress((void**)&pPrHi, g_pr_hi);
    cudaGetSymbolAddress((void**)&pPrLo, g_pr_lo);
    cudaGetSymbolAddress((void**)&pFcHi, g_fc_hi);
    cudaGetSymbolAddress((void**)&pWtHi, g_wt_hi);
    cudaGetSymbolAddress((void**)&pWtLo, g_wt_lo);
    cudaGetSymbolAddress((void**)&pMxHi, g_mx_hi);

    const int SM1   = 4 * 2 * 8192 + 4096;                         // 69632 (dist)
    const int SM3   = 3 * 4 * 8192 + 4096;                         // 102400 (PW)
    const int SMCLS = (128*133 + 128*26 + 128 + 128*26) * 4;       // 95232 (logits+class)
    const int SMLOG = (SM1 > SMCLS) ? SM1 : SMCLS;
    cudaFuncSetAttribute(hmma_gemm_kernel<1,0,4>, cudaFuncAttributeMaxDynamicSharedMemorySize, SM1);
    cudaFuncSetAttribute(hmma_gemm_kernel<1,3,4>, cudaFuncAttributeMaxDynamicSharedMemorySize, SMLOG);
    cudaFuncSetAttribute(hmma_gemm_kernel<3,2,3>, cudaFuncAttributeMaxDynamicSharedMemorySize, SM3);

    prep_kernel<<<PP, 256>>>(protos, lin_w);

    convert_kernel<<<(BB * DD / 4) / 256, 256>>>(patient, pPaHi, BB * DD / 4);
    split_kernel<<<(PP * DD / 4) / 256, 256>>>(protos, pPrHi, pPrLo, PP * DD / 4);
    convert_kernel<<<(PP * DD / 4) / 256, 256>>>(proto_fc_w, pFcHi, PP * DD / 4);
    splitT_kernel<<<dim3(32, 32), 256>>>(bilinear_w, pWtHi, pWtLo);

    // PW = protos @ W  (3-pass, split-K x4: z-slice k range = [z*8, z*8+8))
    hmma_gemm_kernel<3,2,3><<<dim3(DD / 128, PP / 128, 4), 256, SM3>>>(
        pPrHi, pPrLo, pWtHi, pWtLo, nullptr, pPWpart, nullptr, 0, 8);

    reduce_pw_kernel<<<(PP * DD / 4) / 256, 256>>>();

    // distance GEMM (1-pass fp16, deep pipeline) + per-warp top2 candidates
    hmma_gemm_kernel<1,0,4><<<dim3(PP / 128, BB / 128), 256, SM1>>>(
        pPaHi, nullptr, pPrHi, nullptr, pPsq, (float*)pTop2, nullptr, 0, 32);

    argmin_reduce_kernel<<<BB / 8, 256>>>(patient, protos);

    lam_kernel<<<BB / 8, 256>>>(index, bilinear_b, protos);

    mix_kernel<<<BB, 256>>>(index);

    // logits GEMM (1-pass) with smem-staged fused class-head partial epilogue
    hmma_gemm_kernel<1,3,4><<<dim3(PP / 128, BB / 128), 256, SMLOG>>>(
        pMxHi, nullptr, pFcHi, nullptr, proto_fc_b, pPart, class_fc_w, 0, 32);

    reduce_class_kernel<<<(BB * OUTC + 255) / 256, 256>>>(class_fc_b, out);
}

// round 14
// speedup vs baseline: 1.5741x; 1.1038x over previous
#include <cuda_runtime.h>
#include <cuda_fp16.h>
#include <math.h>
#include <stdint.h>

#define BB   16384
#define DD   1024
#define PP   1024
#define OUTC 25
#define NCAND 16            // float4 slots per row (2 candidates each = 32)
#define MARGIN 0.35f

// ---------------- device scratch ----------------
__device__ float g_psq[PP];
__device__ float g_v1[PP];
__device__ float g_v2[PP];
__device__ float g_PW[PP * DD];
__device__ float g_PWpart[(size_t)4 * PP * DD];   // split-K partials
__device__ int   g_labels[BB];
__device__ float g_lam[BB];
__device__ float4 g_top2[(size_t)BB * NCAND];
__device__ float g_part[(size_t)8 * BB * OUTC];   // class-head partials (per col-tile)

__device__ __half g_pa_hi[(size_t)BB * DD];
__device__ __half g_pr_hi[(size_t)PP * DD];
__device__ __half g_pr_lo[(size_t)PP * DD];
__device__ __half g_fc_hi[(size_t)PP * DD];
__device__ __half g_wt_hi[(size_t)DD * DD];
__device__ __half g_wt_lo[(size_t)DD * DD];
__device__ __half g_mx_hi[(size_t)BB * DD];

// ---------------- helpers ----------------
__device__ __forceinline__ uint32_t smem_u32(const void* p) {
    uint32_t a;
    asm("{ .reg .u64 t; cvta.to.shared.u64 t, %1; cvt.u32.u64 %0, t; }" : "=r"(a) : "l"(p));
    return a;
}
__device__ __forceinline__ void ldsm4(uint32_t r[4], uint32_t addr) {
    asm volatile("ldmatrix.sync.aligned.m8n8.x4.shared.b16 {%0,%1,%2,%3}, [%4];"
                 : "=r"(r[0]), "=r"(r[1]), "=r"(r[2]), "=r"(r[3]) : "r"(addr));
}
__device__ __forceinline__ void mma16816(float c[4], const uint32_t a[4],
                                         uint32_t b0, uint32_t b1) {
    asm volatile("mma.sync.aligned.m16n8k16.row.col.f32.f16.f16.f32 "
                 "{%0,%1,%2,%3}, {%4,%5,%6,%7}, {%8,%9}, {%0,%1,%2,%3};"
                 : "+f"(c[0]), "+f"(c[1]), "+f"(c[2]), "+f"(c[3])
                 : "r"(a[0]), "r"(a[1]), "r"(a[2]), "r"(a[3]), "r"(b0), "r"(b1));
}
__device__ __forceinline__ uint32_t pk2h(float a, float b) {
    __half2 t;
    t.x = __float2half(a); t.y = __float2half(b);
    return *reinterpret_cast<uint32_t*>(&t);
}
__device__ __forceinline__ void top2_upd(float s, int idx, float& v1, int& i1,
                                         float& v2, int& i2) {
    if (s < v1 || (s == v1 && idx < i1)) { v2 = v1; i2 = i1; v1 = s; i1 = idx; }
    else if (s < v2 || (s == v2 && idx < i2)) { v2 = s; i2 = idx; }
}
__device__ __forceinline__ void top2_merge(float w1, int j1, float w2, int j2,
                                           float& v1, int& i1, float& v2, int& i2) {
    top2_upd(w1, j1, v1, i1, v2, i2);
    top2_upd(w2, j2, v1, i1, v2, i2);
}

// =================================================================
// prep: p_sq, v1, v2
// =================================================================
__global__ __launch_bounds__(256) void prep_kernel(
    const float* __restrict__ protos, const float* __restrict__ lin_w)
{
    int p = blockIdx.x, t = threadIdx.x;
    float sq = 0.f, a1 = 0.f, a2 = 0.f;
    const float* row = protos + (size_t)p * DD;
    for (int k = t; k < DD; k += 256) {
        float v = row[k];
        sq = fmaf(v, v, sq);
        a1 = fmaf(v, lin_w[k], a1);
        a2 = fmaf(v, lin_w[DD + k], a2);
    }
    __shared__ float s1[256], s2[256], s3[256];
    s1[t] = sq; s2[t] = a1; s3[t] = a2;
    __syncthreads();
    for (int off = 128; off; off >>= 1) {
        if (t < off) { s1[t] += s1[t+off]; s2[t] += s2[t+off]; s3[t] += s3[t+off]; }
        __syncthreads();
    }
    if (t == 0) { g_psq[p] = s1[0]; g_v1[p] = s2[0]; g_v2[p] = s3[0]; }
}

// =================================================================
// convert fp32 -> fp16 (hi only)
// =================================================================
__global__ __launch_bounds__(256) void convert_kernel(
    const float* __restrict__ src, __half* __restrict__ hi, int n4)
{
    int i = blockIdx.x * 256 + threadIdx.x;
    if (i >= n4) return;
    float4 v = reinterpret_cast<const float4*>(src)[i];
    reinterpret_cast<uint32_t*>(hi)[2*i]   = pk2h(v.x, v.y);
    reinterpret_cast<uint32_t*>(hi)[2*i+1] = pk2h(v.z, v.w);
}

// =================================================================
// split fp32 -> fp16 hi + lo
// =================================================================
__global__ __launch_bounds__(256) void split_kernel(
    const float* __restrict__ src, __half* __restrict__ hi,
    __half* __restrict__ lo, int n4)
{
    int i = blockIdx.x * 256 + threadIdx.x;
    if (i >= n4) return;
    float4 v = reinterpret_cast<const float4*>(src)[i];
    uint32_t h0 = pk2h(v.x, v.y), h1 = pk2h(v.z, v.w);
    __half2* hv0 = reinterpret_cast<__half2*>(&h0);
    __half2* hv1 = reinterpret_cast<__half2*>(&h1);
    uint32_t l0 = pk2h(v.x - __half2float(hv0->x), v.y - __half2float(hv0->y));
    uint32_t l1 = pk2h(v.z - __half2float(hv1->x), v.w - __half2float(hv1->y));
    reinterpret_cast<uint32_t*>(hi)[2*i]   = h0;
    reinterpret_cast<uint32_t*>(hi)[2*i+1] = h1;
    reinterpret_cast<uint32_t*>(lo)[2*i]   = l0;
    reinterpret_cast<uint32_t*>(lo)[2*i+1] = l1;
}

// =================================================================
// transpose + split: WT[n][k] = W[k][n], fp16 hi/lo
// =================================================================
__global__ __launch_bounds__(256) void splitT_kernel(
    const float* __restrict__ W, __half* __restrict__ hiT,
    __half* __restrict__ loT)
{
    __shared__ float tile[32][33];
    int n0 = blockIdx.x * 32, k0 = blockIdx.y * 32;
    int tx = threadIdx.x & 31, ty = threadIdx.x >> 5;
#pragma unroll
    for (int i = 0; i < 4; i++) {
        int kk = ty + i * 8;
        tile[kk][tx] = W[(size_t)(k0 + kk) * DD + n0 + tx];
    }
    __syncthreads();
#pragma unroll
    for (int i = 0; i < 4; i++) {
        int a = ty + i * 8;
        float v = tile[tx][a];
        __half h = __float2half(v);
        hiT[(size_t)(n0 + a) * DD + k0 + tx] = h;
        loT[(size_t)(n0 + a) * DD + k0 + tx] = __float2half(v - __half2float(h));
    }
}

// =================================================================
// OLD BK=32 kernel, kept ONLY for the PW 3-pass split-K GEMM (MODE 2).
// =================================================================
template <int PASSES, int MODE, int NST>
__global__ __launch_bounds__(256)
void hmma_gemm_kernel(const __half* __restrict__ Ahi, const __half* __restrict__ Alo,
                      const __half* __restrict__ Bhi, const __half* __restrict__ Blo,
                      const float* __restrict__ bias, float* __restrict__ outp,
                      const float* __restrict__ cw, int kbase, int nkIter)
{
    constexpr int TILES = (PASSES == 3) ? 4 : 2;
    constexpr int STB = TILES * 8192;
    constexpr int BOFF = (PASSES == 1) ? 8192 : 16384;
    constexpr int DEPTH = NST - 1;
    extern __shared__ char smem[];
    const uint32_t sb = smem_u32(smem);
    const int tid = threadIdx.x;
    const int lane = tid & 31;
    const int w = tid >> 5;
    const int wm = w & 3;
    const int wn = w >> 2;
    const int row0 = blockIdx.y * 128;
    const int col0 = blockIdx.x * 128;

    if (MODE == 2) kbase += blockIdx.z * nkIter;   // split-K: per-z K offset

    const int q  = lane >> 3;
    const int lr = lane & 7;
    const int achk = q >> 1;
    const int bchk = q & 1;
    int arow[2], brow[4];
#pragma unroll
    for (int mi = 0; mi < 2; mi++) arow[mi] = wm*32 + mi*16 + ((q & 1) << 3) + lr;
#pragma unroll
    for (int ng = 0; ng < 4; ng++) brow[ng] = wn*64 + ng*16 + ((q >> 1) << 3) + lr;

    float c[2][8][4];
#pragma unroll
    for (int mi = 0; mi < 2; mi++)
#pragma unroll
        for (int nf = 0; nf < 8; nf++)
#pragma unroll
            for (int j = 0; j < 4; j++) c[mi][nf][j] = 0.f;

    auto issue = [&](int st, int kt) {
        const int k0 = (kbase + kt) << 5;
        const uint32_t sbase = sb + st * STB;
#pragma unroll
        for (int it = 0; it < TILES * 2; it++) {
            int ch = it * 256 + tid;
            int t = ch >> 9;
            int within = ch & 511;
            int r = within >> 2, cc = within & 3;
            const __half* src;
            int rbase;
            if (PASSES == 1) {
                src = (t == 0) ? Ahi : Bhi;
                rbase = (t == 0) ? row0 : col0;
            } else {
                src = (t == 0) ? Ahi : (t == 1) ? Alo : (t == 2) ? Bhi : Blo;
                rbase = (t < 2) ? row0 : col0;
            }
            const void* g = src + (size_t)(rbase + r) * DD + k0 + cc * 8;
            uint32_t s = sbase + t * 8192 + r * 64 + ((cc ^ ((r >> 1) & 3)) << 4);
            asm volatile("cp.async.cg.shared.global [%0], [%1], 16;" :: "r"(s), "l"(g));
        }
        asm volatile("cp.async.commit_group;" ::: "memory");
    };

    auto compute = [&](int st) {
        const uint32_t sbase = sb + st * STB;
#pragma unroll
        for (int ks = 0; ks < 2; ks++) {
            uint32_t ah[2][4], al[2][4], bh[4][4], bl[4][4];
#pragma unroll
            for (int mi = 0; mi < 2; mi++) {
                uint32_t ra = sbase + arow[mi] * 64 +
                              ((((ks << 1) | achk) ^ ((arow[mi] >> 1) & 3)) << 4);
                ldsm4(ah[mi], ra);
                if (PASSES == 3) ldsm4(al[mi], ra + 8192);
            }
#pragma unroll
            for (int ng = 0; ng < 4; ng++) {
                uint32_t rb = sbase + BOFF + brow[ng] * 64 +
                              ((((ks << 1) | bchk) ^ ((brow[ng] >> 1) & 3)) << 4);
                ldsm4(bh[ng], rb);
                if (PASSES == 3) ldsm4(bl[ng], rb + 8192);
            }
#pragma unroll
            for (int mi = 0; mi < 2; mi++)
#pragma unroll
                for (int ng = 0; ng < 4; ng++)
#pragma unroll
                    for (int h = 0; h < 2; h++) {
                        int nf = ng * 2 + h;
                        mma16816(c[mi][nf], ah[mi], bh[ng][h*2], bh[ng][h*2+1]);
                        if (PASSES == 3) {
                            mma16816(c[mi][nf], ah[mi], bl[ng][h*2], bl[ng][h*2+1]);
                            mma16816(c[mi][nf], al[mi], bh[ng][h*2], bh[ng][h*2+1]);
                        }
                    }
        }
    };

    const int NK = nkIter;
#pragma unroll
    for (int i = 0; i < DEPTH; i++) issue(i, i);
    for (int kt = 0; kt < NK; kt++) {
        const int rem = NK - 1 - kt;
        if (rem >= 1)      asm volatile("cp.async.wait_group 1;" ::: "memory");
        else               asm volatile("cp.async.wait_group 0;" ::: "memory");
        __syncthreads();
        compute(kt % NST);
        if (kt + DEPTH < NK) issue((kt + DEPTH) % NST, kt + DEPTH);
        __syncthreads();
    }
    __syncthreads();

    // MODE 2 only (PW split-K partial store)
    float* dstp = outp + (size_t)blockIdx.z * PP * DD;
#pragma unroll
    for (int mi = 0; mi < 2; mi++)
#pragma unroll
        for (int rh = 0; rh < 2; rh++) {
            int r = row0 + wm*32 + mi*16 + rh*8 + (lane >> 2);
#pragma unroll
            for (int nf = 0; nf < 8; nf++) {
                int col = col0 + wn*64 + nf*8 + ((lane & 3) << 1);
                float2 o = {c[mi][nf][rh*2], c[mi][nf][rh*2+1]};
                *reinterpret_cast<float2*>(&dstp[(size_t)r * DD + col]) = o;
            }
        }
}

// =================================================================
// NEW BK=64 1-pass fp16 GEMM. 128x128 tile, 128B smem rows (SW128),
// NST=3 stages of 32KB, ONE __syncthreads per iteration.
// MODE 0: per-warp top2(psq-2*dot) -> g_top2
// MODE 3: class-head fusion: stage C to smem, leaky(C+bias).cw -> g_part
// =================================================================
template <int MODE>
__global__ __launch_bounds__(256)
void hmma64_kernel(const __half* __restrict__ A, const __half* __restrict__ B,
                   const float* __restrict__ bias, float* __restrict__ outp,
                   const float* __restrict__ cw)
{
    constexpr int STB = 32768;      // 2 tiles x 16KB
    constexpr int NST = 3;
    constexpr int DEPTH = 2;
    extern __shared__ char smem[];
    const uint32_t sb = smem_u32(smem);
    const int tid = threadIdx.x;
    const int lane = tid & 31;
    const int w = tid >> 5;
    const int wm = w & 3;
    const int wn = w >> 2;
    const int row0 = blockIdx.y * 128;
    const int col0 = blockIdx.x * 128;

    const int q  = lane >> 3;
    const int lr = lane & 7;
    const int achk = q >> 1;
    const int bchk = q & 1;
    int arow[2], brow[4];
#pragma unroll
    for (int mi = 0; mi < 2; mi++) arow[mi] = wm*32 + mi*16 + ((q & 1) << 3) + lr;
#pragma unroll
    for (int ng = 0; ng < 4; ng++) brow[ng] = wn*64 + ng*16 + ((q >> 1) << 3) + lr;

    float c[2][8][4];
#pragma unroll
    for (int mi = 0; mi < 2; mi++)
#pragma unroll
        for (int nf = 0; nf < 8; nf++)
#pragma unroll
            for (int j = 0; j < 4; j++) c[mi][nf][j] = 0.f;

    auto issue = [&](int st, int kt) {
        const int k0 = kt << 6;
        const uint32_t sbase = sb + st * STB;
#pragma unroll
        for (int it = 0; it < 8; it++) {
            int ch = it * 256 + tid;
            int t = ch >> 10;                 // 0 = A, 1 = B (1024 chunks each)
            int within = ch & 1023;
            int r = within >> 3, cc = within & 7;
            const __half* src = t ? B : A;
            int rbase = t ? col0 : row0;
            const void* g = src + (size_t)(rbase + r) * DD + k0 + cc * 8;
            uint32_t s = sbase + t * 16384 + r * 128 + (((uint32_t)(cc ^ (r & 7))) << 4);
            asm volatile("cp.async.cg.shared.global [%0], [%1], 16;" :: "r"(s), "l"(g));
        }
        asm volatile("cp.async.commit_group;" ::: "memory");
    };

    auto compute = [&](int st) {
        const uint32_t sbase = sb + st * STB;
#pragma unroll
        for (int ks = 0; ks < 4; ks++) {
            uint32_t ah[2][4], bh[4][4];
#pragma unroll
            for (int mi = 0; mi < 2; mi++) {
                uint32_t ra = sbase + arow[mi] * 128 +
                              ((uint32_t)((((ks << 1) | achk)) ^ (arow[mi] & 7)) << 4);
                ldsm4(ah[mi], ra);
            }
#pragma unroll
            for (int ng = 0; ng < 4; ng++) {
                uint32_t rb = sbase + 16384 + brow[ng] * 128 +
                              ((uint32_t)((((ks << 1) | bchk)) ^ (brow[ng] & 7)) << 4);
                ldsm4(bh[ng], rb);
            }
#pragma unroll
            for (int mi = 0; mi < 2; mi++)
#pragma unroll
                for (int ng = 0; ng < 4; ng++)
#pragma unroll
                    for (int h = 0; h < 2; h++)
                        mma16816(c[mi][ng*2+h], ah[mi], bh[ng][h*2], bh[ng][h*2+1]);
        }
    };

    const int NK = DD / 64;    // 16
    issue(0, 0);
    issue(1, 1);
    for (int kt = 0; kt < NK; kt++) {
        if (kt < NK - 1) asm volatile("cp.async.wait_group 1;" ::: "memory");
        else             asm volatile("cp.async.wait_group 0;" ::: "memory");
        __syncthreads();
        compute(kt % NST);
        if (kt + DEPTH < NK) issue((kt + DEPTH) % NST, kt + DEPTH);
    }
    __syncthreads();

    if (MODE == 0) {
#pragma unroll
        for (int mi = 0; mi < 2; mi++)
#pragma unroll
            for (int rh = 0; rh < 2; rh++) {
                int lrow_ = wm*32 + mi*16 + rh*8 + (lane >> 2);
                float v1 = 3.4e38f, v2 = 3.4e38f;
                int i1 = 0, i2 = 0;
#pragma unroll
                for (int nf = 0; nf < 8; nf++) {
                    int col = col0 + wn*64 + nf*8 + ((lane & 3) << 1);
                    float s0 = bias[col]     - 2.f * c[mi][nf][rh*2];
                    float s1 = bias[col + 1] - 2.f * c[mi][nf][rh*2+1];
                    top2_upd(s0, col,     v1, i1, v2, i2);
                    top2_upd(s1, col + 1, v1, i1, v2, i2);
                }
#pragma unroll
                for (int d = 1; d <= 2; d <<= 1) {
                    float w1 = __shfl_xor_sync(0xffffffffu, v1, d);
                    float w2 = __shfl_xor_sync(0xffffffffu, v2, d);
                    int   j1 = __shfl_xor_sync(0xffffffffu, i1, d);
                    int   j2 = __shfl_xor_sync(0xffffffffu, i2, d);
                    top2_merge(w1, j1, w2, j2, v1, i1, v2, i2);
                }
                if ((lane & 3) == 0)
                    reinterpret_cast<float4*>(outp)[(size_t)(row0 + lrow_) * NCAND
                                                    + blockIdx.x * 2 + wn] =
                        make_float4(v1, __int_as_float(i1), v2, __int_as_float(i2));
            }
    } else {
        // MODE 3: stage C to smem (stride 133), then class-head partial.
        float* cbuf = reinterpret_cast<float*>(smem);                  // [128][133]
        float* cwsm = cbuf + 128 * 133;                                // [128][26]
        float* bsm  = cwsm + 128 * 26;                                 // [128]
        float* red  = bsm + 128;                                       // [128][26]
#pragma unroll
        for (int mi = 0; mi < 2; mi++)
#pragma unroll
            for (int rh = 0; rh < 2; rh++) {
                int r = wm*32 + mi*16 + rh*8 + (lane >> 2);
#pragma unroll
                for (int nf = 0; nf < 8; nf++) {
                    int cl = wn*64 + nf*8 + ((lane & 3) << 1);
                    cbuf[r * 133 + cl]     = c[mi][nf][rh*2];
                    cbuf[r * 133 + cl + 1] = c[mi][nf][rh*2+1];
                }
            }
        for (int i = tid; i < 128 * 32; i += 256) {
            int cl = i >> 5;
            int o = i & 31;
            if (o < OUTC) cwsm[cl * 26 + o] = cw[(size_t)o * PP + col0 + cl];
        }
        if (tid < 128) bsm[tid] = bias[col0 + tid];
        __syncthreads();

        const int row = tid & 127;
        const int kh = tid >> 7;
        float acc[OUTC];
#pragma unroll
        for (int o = 0; o < OUTC; o++) acc[o] = 0.f;
#pragma unroll 4
        for (int kk = 0; kk < 64; kk++) {
            int cl = kh * 64 + kk;
            float v = cbuf[row * 133 + cl] + bsm[cl];
            v = v > 0.f ? v : 0.01f * v;
#pragma unroll
            for (int o = 0; o < OUTC; o++)
                acc[o] = fmaf(v, cwsm[cl * 26 + o], acc[o]);
        }
        if (kh == 1) {
#pragma unroll
            for (int o = 0; o < OUTC; o++) red[row * 26 + o] = acc[o];
        }
        __syncthreads();
        if (kh == 0) {
            float* dst = outp + ((size_t)blockIdx.x * BB + row0 + row) * OUTC;
#pragma unroll
            for (int o = 0; o < OUTC; o++)
                dst[o] = acc[o] + red[row * 26 + o];
        }
    }
}

// =================================================================
// reduce PW split-K partials (float4 vectorized)
// =================================================================
__global__ __launch_bounds__(256)
void reduce_pw_kernel()
{
    int i = blockIdx.x * 256 + threadIdx.x;     // over PP*DD/4
    const float4* p0 = reinterpret_cast<const float4*>(g_PWpart);
    const size_t stride = (size_t)PP * DD / 4;
    float4 a = p0[i];
    float4 b = p0[i + stride];
    float4 c = p0[i + 2 * stride];
    float4 d = p0[i + 3 * stride];
    float4 s;
    s.x = (a.x + b.x) + (c.x + d.x);
    s.y = (a.y + b.y) + (c.y + d.y);
    s.z = (a.z + b.z) + (c.z + d.z);
    s.w = (a.w + b.w) + (c.w + d.w);
    reinterpret_cast<float4*>(g_PW)[i] = s;
}

// =================================================================
// reduce class partials: out[b][o] = sum_t part[t][b][o] + cb[o]
// =================================================================
__global__ __launch_bounds__(256)
void reduce_class_kernel(const float* __restrict__ cb, float* __restrict__ out)
{
    int i = blockIdx.x * 256 + threadIdx.x;
    if (i >= BB * OUTC) return;
    int o = i % OUTC;
    float s = cb[o];
#pragma unroll
    for (int t = 0; t < 8; t++)
        s += g_part[(size_t)t * BB * OUTC + i];
    out[i] = s;
}

// =================================================================
// 32 candidates/row; exact fp64 rescue over all within MARGIN
// =================================================================
__global__ __launch_bounds__(256)
void argmin_reduce_kernel(const float* __restrict__ patient, const float* __restrict__ protos)
{
    int w = (blockIdx.x * 256 + threadIdx.x) >> 5;
    int lane = threadIdx.x & 31;
    if (w >= BB) return;

    float4 qd = g_top2[(size_t)w * NCAND + (lane >> 1)];
    float val;
    int idx;
    if (lane & 1) { val = qd.z; idx = __float_as_int(qd.w); }
    else          { val = qd.x; idx = __float_as_int(qd.y); }

    float vmin = val;
#pragma unroll
    for (int d = 16; d; d >>= 1)
        vmin = fminf(vmin, __shfl_xor_sync(0xffffffffu, vmin, d));

    bool flag = (val < vmin + MARGIN);
    unsigned mask = __ballot_sync(0xffffffffu, flag);

    if (__popc(mask) == 1) {
        if (flag) g_labels[w] = idx;
        return;
    }

    const float* x = patient + (size_t)w * DD;
    double bestd = 1.0e300;
    int besti = 0x7FFFFFFF;
    while (mask) {
        int src = __ffs(mask) - 1;
        mask &= mask - 1;
        int ci = __shfl_sync(0xffffffffu, idx, src);
        const float* pr = protos + (size_t)ci * DD;
        double acc = 0.0;
        for (int k = lane; k < DD; k += 32)
            acc += (double)x[k] * (double)pr[k];
#pragma unroll
        for (int d = 16; d; d >>= 1)
            acc += __shfl_down_sync(0xffffffffu, acc, d);
        if (lane == 0) {
            double d2 = (double)g_psq[ci] - 2.0 * acc;
            if (d2 < bestd || (d2 == bestd && ci < besti)) { bestd = d2; besti = ci; }
        }
    }
    if (lane == 0) g_labels[w] = besti;
}

// =================================================================
// lam[b] = sigmoid(PW[la].protos[lb] + bil_b + v1[la] + v2[lb])
// =================================================================
__global__ __launch_bounds__(256)
void lam_kernel(const int* __restrict__ index, const float* __restrict__ bilinear_b,
                const float* __restrict__ protos)
{
    int w = (blockIdx.x * 256 + threadIdx.x) >> 5;
    int lane = threadIdx.x & 31;
    if (w >= BB) return;
    int la = g_labels[w];
    int lb = g_labels[index[w]];
    const float4* a = reinterpret_cast<const float4*>(g_PW + (size_t)la * DD);
    const float4* p = reinterpret_cast<const float4*>(protos + (size_t)lb * DD);
    float acc = 0.f;
    for (int k = lane; k < DD / 4; k += 32) {
        float4 u = a[k], v = p[k];
        acc = fmaf(u.x, v.x, acc); acc = fmaf(u.y, v.y, acc);
        acc = fmaf(u.z, v.z, acc); acc = fmaf(u.w, v.w, acc);
    }
#pragma unroll
    for (int off = 16; off; off >>= 1) acc += __shfl_down_sync(0xffffffffu, acc, off);
    if (lane == 0) {
        float s = acc + bilinear_b[0] + g_v1[la] + g_v2[lb];
        g_lam[w] = 1.f / (1.f + expf(-s));
    }
}

// =================================================================
// mixed = lam*x + (1-lam)*x[index], from fp16 pa_hi; emit fp16
// =================================================================
__global__ __launch_bounds__(256)
void mix_kernel(const int* __restrict__ index)
{
    int b = blockIdx.x;
    float lam = g_lam[b], oml = 1.f - lam;
    int ib = index[b];
    int t = threadIdx.x;
    uint2 av = reinterpret_cast<const uint2*>(g_pa_hi + (size_t)b * DD)[t];
    uint2 cv = reinterpret_cast<const uint2*>(g_pa_hi + (size_t)ib * DD)[t];
    __half2 a0 = *reinterpret_cast<__half2*>(&av.x);
    __half2 a1 = *reinterpret_cast<__half2*>(&av.y);
    __half2 c0 = *reinterpret_cast<__half2*>(&cv.x);
    __half2 c1 = *reinterpret_cast<__half2*>(&cv.y);
    float m0 = lam * __half2float(a0.x) + oml * __half2float(c0.x);
    float m1 = lam * __half2float(a0.y) + oml * __half2float(c0.y);
    float m2 = lam * __half2float(a1.x) + oml * __half2float(c1.x);
    float m3 = lam * __half2float(a1.y) + oml * __half2float(c1.y);
    uint2 o;
    o.x = pk2h(m0, m1);
    o.y = pk2h(m2, m3);
    reinterpret_cast<uint2*>(g_mx_hi + (size_t)b * DD)[t] = o;
}

// =================================================================
// launch
// =================================================================
extern "C" void kernel_launch(void* const* d_in, const int* in_sizes, int n_in,
                              void* d_out, int out_size)
{
    const float* patient    = (const float*)d_in[0];
    const float* protos     = (const float*)d_in[1];
    const int*   index      = (const int*)  d_in[2];
    const float* bilinear_w = (const float*)d_in[3];
    const float* bilinear_b = (const float*)d_in[4];
    const float* lin_w      = (const float*)d_in[5];
    const float* proto_fc_w = (const float*)d_in[6];
    const float* proto_fc_b = (const float*)d_in[7];
    const float* class_fc_w = (const float*)d_in[8];
    const float* class_fc_b = (const float*)d_in[9];
    float* out = (float*)d_out;

    float *pPsq, *pPart, *pPWpart;
    float4* pTop2;
    __half *pPaHi, *pPrHi, *pPrLo, *pFcHi, *pWtHi, *pWtLo, *pMxHi;
    cudaGetSymbolAddress((void**)&pPsq, g_psq);
    cudaGetSymbolAddress((void**)&pPart, g_part);
    cudaGetSymbolAddress((void**)&pPWpart, g_PWpart);
    cudaGetSymbolAddress((void**)&pTop2, g_top2);
    cudaGetSymbolAddress((void**)&pPaHi, g_pa_hi);
    cudaGetSymbolAddress((void**)&pPrHi, g_pr_hi);
    cudaGetSymbolAddress((void**)&pPrLo, g_pr_lo);
    cudaGetSymbolAddress((void**)&pFcHi, g_fc_hi);
    cudaGetSymbolAddress((void**)&pWtHi, g_wt_hi);
    cudaGetSymbolAddress((void**)&pWtLo, g_wt_lo);
    cudaGetSymbolAddress((void**)&pMxHi, g_mx_hi);

    const int SM64  = 3 * 32768;                                   // 98304 (BK64, 3 stages)
    const int SM3   = 3 * 4 * 8192 + 4096;                         // 102400 (PW BK32)
    const int SMCLS = (128*133 + 128*26 + 128 + 128*26) * 4;       // 95232
    const int SMLOG = (SM64 > SMCLS) ? SM64 : SMCLS;               // 98304
    cudaFuncSetAttribute(hmma64_kernel<0>, cudaFuncAttributeMaxDynamicSharedMemorySize, SM64);
    cudaFuncSetAttribute(hmma64_kernel<3>, cudaFuncAttributeMaxDynamicSharedMemorySize, SMLOG);
    cudaFuncSetAttribute(hmma_gemm_kernel<3,2,3>, cudaFuncAttributeMaxDynamicSharedMemorySize, SM3);

    prep_kernel<<<PP, 256>>>(protos, lin_w);

    convert_kernel<<<(BB * DD / 4) / 256, 256>>>(patient, pPaHi, BB * DD / 4);
    split_kernel<<<(PP * DD / 4) / 256, 256>>>(protos, pPrHi, pPrLo, PP * DD / 4);
    convert_kernel<<<(PP * DD / 4) / 256, 256>>>(proto_fc_w, pFcHi, PP * DD / 4);
    splitT_kernel<<<dim3(32, 32), 256>>>(bilinear_w, pWtHi, pWtLo);

    // PW = protos @ W  (3-pass BK32, split-K x4: z-slice k = [z*8, z*8+8))
    hmma_gemm_kernel<3,2,3><<<dim3(DD / 128, PP / 128, 4), 256, SM3>>>(
        pPrHi, pPrLo, pWtHi, pWtLo, nullptr, pPWpart, nullptr, 0, 8);

    reduce_pw_kernel<<<(PP * DD / 4) / 256, 256>>>();

    // distance GEMM (1-pass fp16, BK64) + per-warp top2 candidates
    hmma64_kernel<0><<<dim3(PP / 128, BB / 128), 256, SM64>>>(
        pPaHi, pPrHi, pPsq, (float*)pTop2, nullptr);

    argmin_reduce_kernel<<<BB / 8, 256>>>(patient, protos);

    lam_kernel<<<BB / 8, 256>>>(index, bilinear_b, protos);

    mix_kernel<<<BB, 256>>>(index);

    // logits GEMM (1-pass fp16, BK64) with fused class-head partial epilogue
    hmma64_kernel<3><<<dim3(PP / 128, BB / 128), 256, SMLOG>>>(
        pMxHi, pFcHi, proto_fc_b, pPart, class_fc_w);

    reduce_class_kernel<<<(BB * OUTC + 255) / 256, 256>>>(class_fc_b, out);
}

// round 15
// speedup vs baseline: 1.6438x; 1.0443x over previous
#include <cuda_runtime.h>
#include <cuda_fp16.h>
#include <math.h>
#include <stdint.h>

#define BB   16384
#define DD   1024
#define PP   1024
#define OUTC 25
#define NCAND 16            // float4 slots per row (2 candidates each = 32)
#define MARGIN 0.35f

// ---------------- device scratch ----------------
__device__ float g_psq[PP];
__device__ float g_v1[PP];
__device__ float g_v2[PP];
__device__ float g_PW[PP * DD];
__device__ float g_PWpart[(size_t)4 * PP * DD];   // split-K partials
__device__ int   g_labels[BB];
__device__ float4 g_top2[(size_t)BB * NCAND];
__device__ float g_part[(size_t)8 * BB * OUTC];   // class-head partials (per col-tile)

__device__ __half g_pa_hi[(size_t)BB * DD];
__device__ __half g_pr_hi[(size_t)PP * DD];
__device__ __half g_pr_lo[(size_t)PP * DD];
__device__ __half g_fc_hi[(size_t)PP * DD];
__device__ __half g_wt_hi[(size_t)DD * DD];
__device__ __half g_wt_lo[(size_t)DD * DD];
__device__ __half g_mx_hi[(size_t)BB * DD];

// ---------------- helpers ----------------
__device__ __forceinline__ uint32_t smem_u32(const void* p) {
    uint32_t a;
    asm("{ .reg .u64 t; cvta.to.shared.u64 t, %1; cvt.u32.u64 %0, t; }" : "=r"(a) : "l"(p));
    return a;
}
__device__ __forceinline__ void ldsm4(uint32_t r[4], uint32_t addr) {
    asm volatile("ldmatrix.sync.aligned.m8n8.x4.shared.b16 {%0,%1,%2,%3}, [%4];"
                 : "=r"(r[0]), "=r"(r[1]), "=r"(r[2]), "=r"(r[3]) : "r"(addr));
}
__device__ __forceinline__ void mma16816(float c[4], const uint32_t a[4],
                                         uint32_t b0, uint32_t b1) {
    asm volatile("mma.sync.aligned.m16n8k16.row.col.f32.f16.f16.f32 "
                 "{%0,%1,%2,%3}, {%4,%5,%6,%7}, {%8,%9}, {%0,%1,%2,%3};"
                 : "+f"(c[0]), "+f"(c[1]), "+f"(c[2]), "+f"(c[3])
                 : "r"(a[0]), "r"(a[1]), "r"(a[2]), "r"(a[3]), "r"(b0), "r"(b1));
}
__device__ __forceinline__ uint32_t pk2h(float a, float b) {
    __half2 t;
    t.x = __float2half(a); t.y = __float2half(b);
    return *reinterpret_cast<uint32_t*>(&t);
}
__device__ __forceinline__ void top2_upd(float s, int idx, float& v1, int& i1,
                                         float& v2, int& i2) {
    if (s < v1 || (s == v1 && idx < i1)) { v2 = v1; i2 = i1; v1 = s; i1 = idx; }
    else if (s < v2 || (s == v2 && idx < i2)) { v2 = s; i2 = idx; }
}
__device__ __forceinline__ void top2_merge(float w1, int j1, float w2, int j2,
                                           float& v1, int& i1, float& v2, int& i2) {
    top2_upd(w1, j1, v1, i1, v2, i2);
    top2_upd(w2, j2, v1, i1, v2, i2);
}

// =================================================================
// merged prepare kernel: 5 former launches, block-range dispatched.
// S0 [0,16384):        patient fp32 -> fp16 (g_pa_hi)
// S1 [16384,17408):    protos fp32 -> fp16 hi/lo (g_pr_hi/lo)
// S2 [17408,18432):    proto_fc_w fp32 -> fp16 (g_fc_hi)
// S3 [18432,19456):    bilinear_w transpose+split (g_wt_hi/lo)
// S4 [19456,20480):    per-proto psq/v1/v2 reduction
// =================================================================
#define NB0 16384
#define NB1 1024
#define NB2 1024
#define NB3 1024
#define NB4 1024
__global__ __launch_bounds__(256)
void prepare_kernel(const float* __restrict__ patient, const float* __restrict__ protos,
                    const float* __restrict__ fcw, const float* __restrict__ W,
                    const float* __restrict__ lin_w)
{
    __shared__ float shbuf[32 * 33];   // unioned: splitT tile / prep reductions
    const int b = blockIdx.x;
    const int t = threadIdx.x;

    if (b < NB0) {
        // patient convert (hi only)
        int i = b * 256 + t;
        float4 v = reinterpret_cast<const float4*>(patient)[i];
        reinterpret_cast<uint32_t*>(g_pa_hi)[2*i]   = pk2h(v.x, v.y);
        reinterpret_cast<uint32_t*>(g_pa_hi)[2*i+1] = pk2h(v.z, v.w);
    } else if (b < NB0 + NB1) {
        // protos split hi/lo
        int i = (b - NB0) * 256 + t;
        float4 v = reinterpret_cast<const float4*>(protos)[i];
        uint32_t h0 = pk2h(v.x, v.y), h1 = pk2h(v.z, v.w);
        __half2* hv0 = reinterpret_cast<__half2*>(&h0);
        __half2* hv1 = reinterpret_cast<__half2*>(&h1);
        uint32_t l0 = pk2h(v.x - __half2float(hv0->x), v.y - __half2float(hv0->y));
        uint32_t l1 = pk2h(v.z - __half2float(hv1->x), v.w - __half2float(hv1->y));
        reinterpret_cast<uint32_t*>(g_pr_hi)[2*i]   = h0;
        reinterpret_cast<uint32_t*>(g_pr_hi)[2*i+1] = h1;
        reinterpret_cast<uint32_t*>(g_pr_lo)[2*i]   = l0;
        reinterpret_cast<uint32_t*>(g_pr_lo)[2*i+1] = l1;
    } else if (b < NB0 + NB1 + NB2) {
        // proto_fc_w convert (hi only)
        int i = (b - NB0 - NB1) * 256 + t;
        float4 v = reinterpret_cast<const float4*>(fcw)[i];
        reinterpret_cast<uint32_t*>(g_fc_hi)[2*i]   = pk2h(v.x, v.y);
        reinterpret_cast<uint32_t*>(g_fc_hi)[2*i+1] = pk2h(v.z, v.w);
    } else if (b < NB0 + NB1 + NB2 + NB3) {
        // bilinear_w transpose + split: WT[n][k] = W[k][n]
        int s = b - NB0 - NB1 - NB2;
        int n0 = (s & 31) * 32, k0 = (s >> 5) * 32;
        int tx = t & 31, ty = t >> 5;
        float (*tile)[33] = reinterpret_cast<float(*)[33]>(shbuf);
#pragma unroll
        for (int i = 0; i < 4; i++) {
            int kk = ty + i * 8;
            tile[kk][tx] = W[(size_t)(k0 + kk) * DD + n0 + tx];
        }
        __syncthreads();
#pragma unroll
        for (int i = 0; i < 4; i++) {
            int a = ty + i * 8;
            float v = tile[tx][a];
            __half h = __float2half(v);
            g_wt_hi[(size_t)(n0 + a) * DD + k0 + tx] = h;
            g_wt_lo[(size_t)(n0 + a) * DD + k0 + tx] = __float2half(v - __half2float(h));
        }
    } else {
        // psq / v1 / v2 reduction for prototype p
        int p = b - NB0 - NB1 - NB2 - NB3;
        float sq = 0.f, a1 = 0.f, a2 = 0.f;
        const float* row = protos + (size_t)p * DD;
        for (int k = t; k < DD; k += 256) {
            float v = row[k];
            sq = fmaf(v, v, sq);
            a1 = fmaf(v, lin_w[k], a1);
            a2 = fmaf(v, lin_w[DD + k], a2);
        }
        float* s1 = shbuf;
        float* s2 = shbuf + 256;
        float* s3 = shbuf + 512;
        s1[t] = sq; s2[t] = a1; s3[t] = a2;
        __syncthreads();
        for (int off = 128; off; off >>= 1) {
            if (t < off) { s1[t] += s1[t+off]; s2[t] += s2[t+off]; s3[t] += s3[t+off]; }
            __syncthreads();
        }
        if (t == 0) { g_psq[p] = s1[0]; g_v1[p] = s2[0]; g_v2[p] = s3[0]; }
    }
}

// =================================================================
// OLD BK=32 kernel, kept ONLY for the PW 3-pass split-K GEMM (MODE 2).
// =================================================================
template <int PASSES, int MODE, int NST>
__global__ __launch_bounds__(256)
void hmma_gemm_kernel(const __half* __restrict__ Ahi, const __half* __restrict__ Alo,
                      const __half* __restrict__ Bhi, const __half* __restrict__ Blo,
                      const float* __restrict__ bias, float* __restrict__ outp,
                      const float* __restrict__ cw, int kbase, int nkIter)
{
    constexpr int TILES = (PASSES == 3) ? 4 : 2;
    constexpr int STB = TILES * 8192;
    constexpr int BOFF = (PASSES == 1) ? 8192 : 16384;
    constexpr int DEPTH = NST - 1;
    extern __shared__ char smem[];
    const uint32_t sb = smem_u32(smem);
    const int tid = threadIdx.x;
    const int lane = tid & 31;
    const int w = tid >> 5;
    const int wm = w & 3;
    const int wn = w >> 2;
    const int row0 = blockIdx.y * 128;
    const int col0 = blockIdx.x * 128;

    if (MODE == 2) kbase += blockIdx.z * nkIter;   // split-K: per-z K offset

    const int q  = lane >> 3;
    const int lr = lane & 7;
    const int achk = q >> 1;
    const int bchk = q & 1;
    int arow[2], brow[4];
#pragma unroll
    for (int mi = 0; mi < 2; mi++) arow[mi] = wm*32 + mi*16 + ((q & 1) << 3) + lr;
#pragma unroll
    for (int ng = 0; ng < 4; ng++) brow[ng] = wn*64 + ng*16 + ((q >> 1) << 3) + lr;

    float c[2][8][4];
#pragma unroll
    for (int mi = 0; mi < 2; mi++)
#pragma unroll
        for (int nf = 0; nf < 8; nf++)
#pragma unroll
            for (int j = 0; j < 4; j++) c[mi][nf][j] = 0.f;

    auto issue = [&](int st, int kt) {
        const int k0 = (kbase + kt) << 5;
        const uint32_t sbase = sb + st * STB;
#pragma unroll
        for (int it = 0; it < TILES * 2; it++) {
            int ch = it * 256 + tid;
            int t = ch >> 9;
            int within = ch & 511;
            int r = within >> 2, cc = within & 3;
            const __half* src;
            int rbase;
            if (PASSES == 1) {
                src = (t == 0) ? Ahi : Bhi;
                rbase = (t == 0) ? row0 : col0;
            } else {
                src = (t == 0) ? Ahi : (t == 1) ? Alo : (t == 2) ? Bhi : Blo;
                rbase = (t < 2) ? row0 : col0;
            }
            const void* g = src + (size_t)(rbase + r) * DD + k0 + cc * 8;
            uint32_t s = sbase + t * 8192 + r * 64 + ((cc ^ ((r >> 1) & 3)) << 4);
            asm volatile("cp.async.cg.shared.global [%0], [%1], 16;" :: "r"(s), "l"(g));
        }
        asm volatile("cp.async.commit_group;" ::: "memory");
    };

    auto compute = [&](int st) {
        const uint32_t sbase = sb + st * STB;
#pragma unroll
        for (int ks = 0; ks < 2; ks++) {
            uint32_t ah[2][4], al[2][4], bh[4][4], bl[4][4];
#pragma unroll
            for (int mi = 0; mi < 2; mi++) {
                uint32_t ra = sbase + arow[mi] * 64 +
                              ((((ks << 1) | achk) ^ ((arow[mi] >> 1) & 3)) << 4);
                ldsm4(ah[mi], ra);
                if (PASSES == 3) ldsm4(al[mi], ra + 8192);
            }
#pragma unroll
            for (int ng = 0; ng < 4; ng++) {
                uint32_t rb = sbase + BOFF + brow[ng] * 64 +
                              ((((ks << 1) | bchk) ^ ((brow[ng] >> 1) & 3)) << 4);
                ldsm4(bh[ng], rb);
                if (PASSES == 3) ldsm4(bl[ng], rb + 8192);
            }
#pragma unroll
            for (int mi = 0; mi < 2; mi++)
#pragma unroll
                for (int ng = 0; ng < 4; ng++)
#pragma unroll
                    for (int h = 0; h < 2; h++) {
                        int nf = ng * 2 + h;
                        mma16816(c[mi][nf], ah[mi], bh[ng][h*2], bh[ng][h*2+1]);
                        if (PASSES == 3) {
                            mma16816(c[mi][nf], ah[mi], bl[ng][h*2], bl[ng][h*2+1]);
                            mma16816(c[mi][nf], al[mi], bh[ng][h*2], bh[ng][h*2+1]);
                        }
                    }
        }
    };

    const int NK = nkIter;
#pragma unroll
    for (int i = 0; i < DEPTH; i++) issue(i, i);
    for (int kt = 0; kt < NK; kt++) {
        const int rem = NK - 1 - kt;
        if (rem >= 1)      asm volatile("cp.async.wait_group 1;" ::: "memory");
        else               asm volatile("cp.async.wait_group 0;" ::: "memory");
        __syncthreads();
        compute(kt % NST);
        if (kt + DEPTH < NK) issue((kt + DEPTH) % NST, kt + DEPTH);
        __syncthreads();
    }
    __syncthreads();

    // MODE 2 only (PW split-K partial store)
    float* dstp = outp + (size_t)blockIdx.z * PP * DD;
#pragma unroll
    for (int mi = 0; mi < 2; mi++)
#pragma unroll
        for (int rh = 0; rh < 2; rh++) {
            int r = row0 + wm*32 + mi*16 + rh*8 + (lane >> 2);
#pragma unroll
            for (int nf = 0; nf < 8; nf++) {
                int col = col0 + wn*64 + nf*8 + ((lane & 3) << 1);
                float2 o = {c[mi][nf][rh*2], c[mi][nf][rh*2+1]};
                *reinterpret_cast<float2*>(&dstp[(size_t)r * DD + col]) = o;
            }
        }
}

// =================================================================
// BK=64 1-pass fp16 GEMM. 128x128 tile, 128B smem rows (SW128),
// NST=3 stages of 32KB, ONE __syncthreads per iteration.
// MODE 0: per-warp top2(psq-2*dot) -> g_top2
// MODE 3: class-head fusion: stage C to smem, leaky(C+bias).cw -> g_part
// =================================================================
template <int MODE>
__global__ __launch_bounds__(256)
void hmma64_kernel(const __half* __restrict__ A, const __half* __restrict__ B,
                   const float* __restrict__ bias, float* __restrict__ outp,
                   const float* __restrict__ cw)
{
    constexpr int STB = 32768;
    constexpr int NST = 3;
    constexpr int DEPTH = 2;
    extern __shared__ char smem[];
    const uint32_t sb = smem_u32(smem);
    const int tid = threadIdx.x;
    const int lane = tid & 31;
    const int w = tid >> 5;
    const int wm = w & 3;
    const int wn = w >> 2;
    const int row0 = blockIdx.y * 128;
    const int col0 = blockIdx.x * 128;

    const int q  = lane >> 3;
    const int lr = lane & 7;
    const int achk = q >> 1;
    const int bchk = q & 1;
    int arow[2], brow[4];
#pragma unroll
    for (int mi = 0; mi < 2; mi++) arow[mi] = wm*32 + mi*16 + ((q & 1) << 3) + lr;
#pragma unroll
    for (int ng = 0; ng < 4; ng++) brow[ng] = wn*64 + ng*16 + ((q >> 1) << 3) + lr;

    float c[2][8][4];
#pragma unroll
    for (int mi = 0; mi < 2; mi++)
#pragma unroll
        for (int nf = 0; nf < 8; nf++)
#pragma unroll
            for (int j = 0; j < 4; j++) c[mi][nf][j] = 0.f;

    auto issue = [&](int st, int kt) {
        const int k0 = kt << 6;
        const uint32_t sbase = sb + st * STB;
#pragma unroll
        for (int it = 0; it < 8; it++) {
            int ch = it * 256 + tid;
            int t = ch >> 10;
            int within = ch & 1023;
            int r = within >> 3, cc = within & 7;
            const __half* src = t ? B : A;
            int rbase = t ? col0 : row0;
            const void* g = src + (size_t)(rbase + r) * DD + k0 + cc * 8;
            uint32_t s = sbase + t * 16384 + r * 128 + (((uint32_t)(cc ^ (r & 7))) << 4);
            asm volatile("cp.async.cg.shared.global [%0], [%1], 16;" :: "r"(s), "l"(g));
        }
        asm volatile("cp.async.commit_group;" ::: "memory");
    };

    auto compute = [&](int st) {
        const uint32_t sbase = sb + st * STB;
#pragma unroll
        for (int ks = 0; ks < 4; ks++) {
            uint32_t ah[2][4], bh[4][4];
#pragma unroll
            for (int mi = 0; mi < 2; mi++) {
                uint32_t ra = sbase + arow[mi] * 128 +
                              ((uint32_t)((((ks << 1) | achk)) ^ (arow[mi] & 7)) << 4);
                ldsm4(ah[mi], ra);
            }
#pragma unroll
            for (int ng = 0; ng < 4; ng++) {
                uint32_t rb = sbase + 16384 + brow[ng] * 128 +
                              ((uint32_t)((((ks << 1) | bchk)) ^ (brow[ng] & 7)) << 4);
                ldsm4(bh[ng], rb);
            }
#pragma unroll
            for (int mi = 0; mi < 2; mi++)
#pragma unroll
                for (int ng = 0; ng < 4; ng++)
#pragma unroll
                    for (int h = 0; h < 2; h++)
                        mma16816(c[mi][ng*2+h], ah[mi], bh[ng][h*2], bh[ng][h*2+1]);
        }
    };

    const int NK = DD / 64;
    issue(0, 0);
    issue(1, 1);
    for (int kt = 0; kt < NK; kt++) {
        if (kt < NK - 1) asm volatile("cp.async.wait_group 1;" ::: "memory");
        else             asm volatile("cp.async.wait_group 0;" ::: "memory");
        __syncthreads();
        compute(kt % NST);
        if (kt + DEPTH < NK) issue((kt + DEPTH) % NST, kt + DEPTH);
    }
    __syncthreads();

    if (MODE == 0) {
#pragma unroll
        for (int mi = 0; mi < 2; mi++)
#pragma unroll
            for (int rh = 0; rh < 2; rh++) {
                int lrow_ = wm*32 + mi*16 + rh*8 + (lane >> 2);
                float v1 = 3.4e38f, v2 = 3.4e38f;
                int i1 = 0, i2 = 0;
#pragma unroll
                for (int nf = 0; nf < 8; nf++) {
                    int col = col0 + wn*64 + nf*8 + ((lane & 3) << 1);
                    float s0 = bias[col]     - 2.f * c[mi][nf][rh*2];
                    float s1 = bias[col + 1] - 2.f * c[mi][nf][rh*2+1];
                    top2_upd(s0, col,     v1, i1, v2, i2);
                    top2_upd(s1, col + 1, v1, i1, v2, i2);
                }
#pragma unroll
                for (int d = 1; d <= 2; d <<= 1) {
                    float w1 = __shfl_xor_sync(0xffffffffu, v1, d);
                    float w2 = __shfl_xor_sync(0xffffffffu, v2, d);
                    int   j1 = __shfl_xor_sync(0xffffffffu, i1, d);
                    int   j2 = __shfl_xor_sync(0xffffffffu, i2, d);
                    top2_merge(w1, j1, w2, j2, v1, i1, v2, i2);
                }
                if ((lane & 3) == 0)
                    reinterpret_cast<float4*>(outp)[(size_t)(row0 + lrow_) * NCAND
                                                    + blockIdx.x * 2 + wn] =
                        make_float4(v1, __int_as_float(i1), v2, __int_as_float(i2));
            }
    } else {
        // MODE 3: stage C to smem (stride 133), then class-head partial.
        float* cbuf = reinterpret_cast<float*>(smem);                  // [128][133]
        float* cwsm = cbuf + 128 * 133;                                // [128][26]
        float* bsm  = cwsm + 128 * 26;                                 // [128]
        float* red  = bsm + 128;                                       // [128][26]
#pragma unroll
        for (int mi = 0; mi < 2; mi++)
#pragma unroll
            for (int rh = 0; rh < 2; rh++) {
                int r = wm*32 + mi*16 + rh*8 + (lane >> 2);
#pragma unroll
                for (int nf = 0; nf < 8; nf++) {
                    int cl = wn*64 + nf*8 + ((lane & 3) << 1);
                    cbuf[r * 133 + cl]     = c[mi][nf][rh*2];
                    cbuf[r * 133 + cl + 1] = c[mi][nf][rh*2+1];
                }
            }
        for (int i = tid; i < 128 * 32; i += 256) {
            int cl = i >> 5;
            int o = i & 31;
            if (o < OUTC) cwsm[cl * 26 + o] = cw[(size_t)o * PP + col0 + cl];
        }
        if (tid < 128) bsm[tid] = bias[col0 + tid];
        __syncthreads();

        const int row = tid & 127;
        const int kh = tid >> 7;
        float acc[OUTC];
#pragma unroll
        for (int o = 0; o < OUTC; o++) acc[o] = 0.f;
#pragma unroll 4
        for (int kk = 0; kk < 64; kk++) {
            int cl = kh * 64 + kk;
            float v = cbuf[row * 133 + cl] + bsm[cl];
            v = v > 0.f ? v : 0.01f * v;
#pragma unroll
            for (int o = 0; o < OUTC; o++)
                acc[o] = fmaf(v, cwsm[cl * 26 + o], acc[o]);
        }
        if (kh == 1) {
#pragma unroll
            for (int o = 0; o < OUTC; o++) red[row * 26 + o] = acc[o];
        }
        __syncthreads();
        if (kh == 0) {
            float* dst = outp + ((size_t)blockIdx.x * BB + row0 + row) * OUTC;
#pragma unroll
            for (int o = 0; o < OUTC; o++)
                dst[o] = acc[o] + red[row * 26 + o];
        }
    }
}

// =================================================================
// reduce PW split-K partials (float4 vectorized)
// =================================================================
__global__ __launch_bounds__(256)
void reduce_pw_kernel()
{
    int i = blockIdx.x * 256 + threadIdx.x;
    const float4* p0 = reinterpret_cast<const float4*>(g_PWpart);
    const size_t stride = (size_t)PP * DD / 4;
    float4 a = p0[i];
    float4 b = p0[i + stride];
    float4 c = p0[i + 2 * stride];
    float4 d = p0[i + 3 * stride];
    float4 s;
    s.x = (a.x + b.x) + (c.x + d.x);
    s.y = (a.y + b.y) + (c.y + d.y);
    s.z = (a.z + b.z) + (c.z + d.z);
    s.w = (a.w + b.w) + (c.w + d.w);
    reinterpret_cast<float4*>(g_PW)[i] = s;
}

// =================================================================
// reduce class partials: out[b][o] = sum_t part[t][b][o] + cb[o]
// =================================================================
__global__ __launch_bounds__(256)
void reduce_class_kernel(const float* __restrict__ cb, float* __restrict__ out)
{
    int i = blockIdx.x * 256 + threadIdx.x;
    if (i >= BB * OUTC) return;
    int o = i % OUTC;
    float s = cb[o];
#pragma unroll
    for (int t = 0; t < 8; t++)
        s += g_part[(size_t)t * BB * OUTC + i];
    out[i] = s;
}

// =================================================================
// 32 candidates/row; exact fp64 rescue over all within MARGIN
// =================================================================
__global__ __launch_bounds__(256)
void argmin_reduce_kernel(const float* __restrict__ patient, const float* __restrict__ protos)
{
    int w = (blockIdx.x * 256 + threadIdx.x) >> 5;
    int lane = threadIdx.x & 31;
    if (w >= BB) return;

    float4 qd = g_top2[(size_t)w * NCAND + (lane >> 1)];
    float val;
    int idx;
    if (lane & 1) { val = qd.z; idx = __float_as_int(qd.w); }
    else          { val = qd.x; idx = __float_as_int(qd.y); }

    float vmin = val;
#pragma unroll
    for (int d = 16; d; d >>= 1)
        vmin = fminf(vmin, __shfl_xor_sync(0xffffffffu, vmin, d));

    bool flag = (val < vmin + MARGIN);
    unsigned mask = __ballot_sync(0xffffffffu, flag);

    if (__popc(mask) == 1) {
        if (flag) g_labels[w] = idx;
        return;
    }

    const float* x = patient + (size_t)w * DD;
    double bestd = 1.0e300;
    int besti = 0x7FFFFFFF;
    while (mask) {
        int src = __ffs(mask) - 1;
        mask &= mask - 1;
        int ci = __shfl_sync(0xffffffffu, idx, src);
        const float* pr = protos + (size_t)ci * DD;
        double acc = 0.0;
        for (int k = lane; k < DD; k += 32)
            acc += (double)x[k] * (double)pr[k];
#pragma unroll
        for (int d = 16; d; d >>= 1)
            acc += __shfl_down_sync(0xffffffffu, acc, d);
        if (lane == 0) {
            double d2 = (double)g_psq[ci] - 2.0 * acc;
            if (d2 < bestd || (d2 == bestd && ci < besti)) { bestd = d2; besti = ci; }
        }
    }
    if (lane == 0) g_labels[w] = besti;
}

// =================================================================
// fused lam + mix: warp computes lam[w] = sigmoid(...), broadcasts it,
// then blends row w: mx_hi = lam*pa_hi[w] + (1-lam)*pa_hi[index[w]]
// =================================================================
__global__ __launch_bounds__(256)
void lam_mix_kernel(const int* __restrict__ index, const float* __restrict__ bilinear_b,
                    const float* __restrict__ protos)
{
    int w = (blockIdx.x * 256 + threadIdx.x) >> 5;
    int lane = threadIdx.x & 31;
    if (w >= BB) return;
    int ib = index[w];
    int la = g_labels[w];
    int lb = g_labels[ib];
    const float4* a = reinterpret_cast<const float4*>(g_PW + (size_t)la * DD);
    const float4* p = reinterpret_cast<const float4*>(protos + (size_t)lb * DD);
    float acc = 0.f;
    for (int k = lane; k < DD / 4; k += 32) {
        float4 u = a[k], v = p[k];
        acc = fmaf(u.x, v.x, acc); acc = fmaf(u.y, v.y, acc);
        acc = fmaf(u.z, v.z, acc); acc = fmaf(u.w, v.w, acc);
    }
#pragma unroll
    for (int off = 16; off; off >>= 1) acc += __shfl_down_sync(0xffffffffu, acc, off);
    float lam;
    if (lane == 0) {
        float s = acc + bilinear_b[0] + g_v1[la] + g_v2[lb];
        lam = 1.f / (1.f + expf(-s));
    }
    lam = __shfl_sync(0xffffffffu, lam, 0);
    float oml = 1.f - lam;

    const uint2* xa = reinterpret_cast<const uint2*>(g_pa_hi + (size_t)w * DD);
    const uint2* xb = reinterpret_cast<const uint2*>(g_pa_hi + (size_t)ib * DD);
    uint2* o = reinterpret_cast<uint2*>(g_mx_hi + (size_t)w * DD);
#pragma unroll
    for (int i = lane; i < 256; i += 32) {
        uint2 av = xa[i], cv = xb[i];
        __half2 a0 = *reinterpret_cast<__half2*>(&av.x);
        __half2 a1 = *reinterpret_cast<__half2*>(&av.y);
        __half2 c0 = *reinterpret_cast<__half2*>(&cv.x);
        __half2 c1 = *reinterpret_cast<__half2*>(&cv.y);
        float m0 = lam * __half2float(a0.x) + oml * __half2float(c0.x);
        float m1 = lam * __half2float(a0.y) + oml * __half2float(c0.y);
        float m2 = lam * __half2float(a1.x) + oml * __half2float(c1.x);
        float m3 = lam * __half2float(a1.y) + oml * __half2float(c1.y);
        uint2 ov;
        ov.x = pk2h(m0, m1);
        ov.y = pk2h(m2, m3);
        o[i] = ov;
    }
}

// =================================================================
// launch
// =================================================================
extern "C" void kernel_launch(void* const* d_in, const int* in_sizes, int n_in,
                              void* d_out, int out_size)
{
    const float* patient    = (const float*)d_in[0];
    const float* protos     = (const float*)d_in[1];
    const int*   index      = (const int*)  d_in[2];
    const float* bilinear_w = (const float*)d_in[3];
    const float* bilinear_b = (const float*)d_in[4];
    const float* lin_w      = (const float*)d_in[5];
    const float* proto_fc_w = (const float*)d_in[6];
    const float* proto_fc_b = (const float*)d_in[7];
    const float* class_fc_w = (const float*)d_in[8];
    const float* class_fc_b = (const float*)d_in[9];
    float* out = (float*)d_out;

    float *pPsq, *pPart, *pPWpart;
    float4* pTop2;
    __half *pPaHi, *pPrHi, *pPrLo, *pFcHi, *pWtHi, *pWtLo, *pMxHi;
    cudaGetSymbolAddress((void**)&pPsq, g_psq);
    cudaGetSymbolAddress((void**)&pPart, g_part);
    cudaGetSymbolAddress((void**)&pPWpart, g_PWpart);
    cudaGetSymbolAddress((void**)&pTop2, g_top2);
    cudaGetSymbolAddress((void**)&pPaHi, g_pa_hi);
    cudaGetSymbolAddress((void**)&pPrHi, g_pr_hi);
    cudaGetSymbolAddress((void**)&pPrLo, g_pr_lo);
    cudaGetSymbolAddress((void**)&pFcHi, g_fc_hi);
    cudaGetSymbolAddress((void**)&pWtHi, g_wt_hi);
    cudaGetSymbolAddress((void**)&pWtLo, g_wt_lo);
    cudaGetSymbolAddress((void**)&pMxHi, g_mx_hi);

    const int SM64  = 3 * 32768;                                   // 98304
    const int SM3   = 3 * 4 * 8192 + 4096;                         // 102400
    const int SMCLS = (128*133 + 128*26 + 128 + 128*26) * 4;       // 95232
    const int SMLOG = (SM64 > SMCLS) ? SM64 : SMCLS;               // 98304
    cudaFuncSetAttribute(hmma64_kernel<0>, cudaFuncAttributeMaxDynamicSharedMemorySize, SM64);
    cudaFuncSetAttribute(hmma64_kernel<3>, cudaFuncAttributeMaxDynamicSharedMemorySize, SMLOG);
    cudaFuncSetAttribute(hmma_gemm_kernel<3,2,3>, cudaFuncAttributeMaxDynamicSharedMemorySize, SM3);

    // one merged prepare pass (converts, splits, transpose-split, psq/v1/v2)
    prepare_kernel<<<NB0 + NB1 + NB2 + NB3 + NB4, 256>>>(
        patient, protos, proto_fc_w, bilinear_w, lin_w);

    // PW = protos @ W  (3-pass BK32, split-K x4: z-slice k = [z*8, z*8+8))
    hmma_gemm_kernel<3,2,3><<<dim3(DD / 128, PP / 128, 4), 256, SM3>>>(
        pPrHi, pPrLo, pWtHi, pWtLo, nullptr, pPWpart, nullptr, 0, 8);

    reduce_pw_kernel<<<(PP * DD / 4) / 256, 256>>>();

    // distance GEMM (1-pass fp16, BK64) + per-warp top2 candidates
    hmma64_kernel<0><<<dim3(PP / 128, BB / 128), 256, SM64>>>(
        pPaHi, pPrHi, pPsq, (float*)pTop2, nullptr);

    argmin_reduce_kernel<<<BB / 8, 256>>>(patient, protos);

    // fused lam + mix
    lam_mix_kernel<<<BB / 8, 256>>>(index, bilinear_b, protos);

    // logits GEMM (1-pass fp16, BK64) with fused class-head partial epilogue
    hmma64_kernel<3><<<dim3(PP / 128, BB / 128), 256, SMLOG>>>(
        pMxHi, pFcHi, proto_fc_b, pPart, class_fc_w);

    reduce_class_kernel<<<(BB * OUTC + 255) / 256, 256>>>(class_fc_b, out);
}